// round 1
// baseline (speedup 1.0000x reference)
#include <cuda_runtime.h>
#include <math.h>

// Problem constants
#define Bb  2
#define Ss  4096
#define Dd  768
#define Hh  12
#define DHh 64

// Scratch (device globals — no allocation allowed)
__device__ float g_Q[(size_t)Bb * Hh * Ss * DHh];   // [B,H,S,DH], pre-scaled by 1/sqrt(DH)
__device__ float g_K[(size_t)Bb * Hh * Ss * DHh];   // [B,H,S,DH]
__device__ float g_V[(size_t)Bb * Hh * Ss * DHh];   // [B,H,S,DH]
__device__ float g_AO[(size_t)Bb * Ss * Dd];        // [B,S,D] attention output

// ---------------------------------------------------------------------------
// SGEMM: out = alpha * (X @ W^T + bias)
//   X: [M, K] row-major, W: [N, K] row-major (nn.Linear weight), bias: [N]
//   mode 0: write out in [B,H,S,DH] layout (m -> (b,s), n -> (h,dh))
//   mode 1: write out row-major [M, N]
// 128x128 block tile, 8x8 per thread, BK=8.
// ---------------------------------------------------------------------------
__global__ void __launch_bounds__(256) sgemm_bias(
    const float* __restrict__ X, const float* __restrict__ W,
    const float* __restrict__ bias, float* __restrict__ out,
    float alpha, int mode)
{
    __shared__ float As[8][132];
    __shared__ float Bs[8][132];

    const int tid = threadIdx.x;
    const int m0 = blockIdx.y * 128;
    const int n0 = blockIdx.x * 128;

    const int lr = tid >> 1;          // 0..127 (row within tile)
    const int lc = (tid & 1) * 4;     // 0 or 4 (k offset)
    const int tx = tid & 15;
    const int ty = tid >> 4;

    const float* Xp = X + (size_t)(m0 + lr) * Dd + lc;
    const float* Wp = W + (size_t)(n0 + lr) * Dd + lc;

    float acc[8][8];
#pragma unroll
    for (int i = 0; i < 8; i++)
#pragma unroll
        for (int j = 0; j < 8; j++) acc[i][j] = 0.f;

    for (int k0 = 0; k0 < Dd; k0 += 8) {
        float4 a = *(const float4*)(Xp + k0);
        float4 b = *(const float4*)(Wp + k0);
        As[lc + 0][lr] = a.x; As[lc + 1][lr] = a.y;
        As[lc + 2][lr] = a.z; As[lc + 3][lr] = a.w;
        Bs[lc + 0][lr] = b.x; Bs[lc + 1][lr] = b.y;
        Bs[lc + 2][lr] = b.z; Bs[lc + 3][lr] = b.w;
        __syncthreads();

#pragma unroll
        for (int k = 0; k < 8; k++) {
            float4 a0 = *(const float4*)&As[k][ty * 4];
            float4 a1 = *(const float4*)&As[k][64 + ty * 4];
            float4 b0 = *(const float4*)&Bs[k][tx * 4];
            float4 b1 = *(const float4*)&Bs[k][64 + tx * 4];
            float av[8] = {a0.x, a0.y, a0.z, a0.w, a1.x, a1.y, a1.z, a1.w};
            float bv[8] = {b0.x, b0.y, b0.z, b0.w, b1.x, b1.y, b1.z, b1.w};
#pragma unroll
            for (int i = 0; i < 8; i++)
#pragma unroll
                for (int j = 0; j < 8; j++)
                    acc[i][j] += av[i] * bv[j];
        }
        __syncthreads();
    }

    // Epilogue
#pragma unroll
    for (int ii = 0; ii < 2; ii++) {
#pragma unroll
        for (int i = 0; i < 4; i++) {
            const int m = m0 + ii * 64 + ty * 4 + i;
            const int bidx = m >> 12;       // m / 4096
            const int sidx = m & 4095;      // m % 4096
#pragma unroll
            for (int jj = 0; jj < 2; jj++) {
                const int n = n0 + jj * 64 + tx * 4;
                float4 r;
                r.x = alpha * (acc[ii * 4 + i][jj * 4 + 0] + bias[n + 0]);
                r.y = alpha * (acc[ii * 4 + i][jj * 4 + 1] + bias[n + 1]);
                r.z = alpha * (acc[ii * 4 + i][jj * 4 + 2] + bias[n + 2]);
                r.w = alpha * (acc[ii * 4 + i][jj * 4 + 3] + bias[n + 3]);
                if (mode == 0) {
                    const int h = n >> 6;
                    const int dh = n & 63;
                    float* p = out + ((size_t)(bidx * Hh + h) * Ss + sidx) * DHh + dh;
                    *(float4*)p = r;
                } else {
                    *(float4*)(out + (size_t)m * Dd + n) = r;
                }
            }
        }
    }
}

// ---------------------------------------------------------------------------
// Flash attention (fp32, online softmax).
// grid: (S/64, B*H), block 256 (16x16 thread grid).
// Per block: 64 Q rows; loops over 64-row KV tiles.
// Score phase:  thread owns score rows ty+16i, cols tx+16j (shfl row-reduce).
// PV phase:     thread owns O rows ty+16i, cols tx*4+j (vectorized V loads).
// Ks buffer (ld=68) is reused to stage P between phases.
// ---------------------------------------------------------------------------
#define KS_LD 68
#define FLASH_SMEM ((64 * 64 + 64 * KS_LD + 64 * 64) * 4)

__global__ void __launch_bounds__(256) flash_attn(
    const float* __restrict__ Q, const float* __restrict__ K,
    const float* __restrict__ V, const float* __restrict__ mask,
    float* __restrict__ AO)
{
    extern __shared__ float sm[];
    float* Qs = sm;                       // [64][64]
    float* Ks = sm + 64 * 64;             // [64][68]  (also P)
    float* Vs = Ks + 64 * KS_LD;          // [64][64]

    const int tid = threadIdx.x;
    const int tx = tid & 15;
    const int ty = tid >> 4;
    const int bh = blockIdx.y;
    const int q0 = blockIdx.x * 64;
    const int b = bh / Hh;
    const int h = bh % Hh;

    const float* Qp = Q + ((size_t)bh * Ss + q0) * DHh;
    const float* Kp = K + (size_t)bh * Ss * DHh;
    const float* Vp = V + (size_t)bh * Ss * DHh;

    // Load Q tile (already scaled by 1/sqrt(DH) at projection time)
    for (int i = tid; i < 64 * DHh / 4; i += 256)
        ((float4*)Qs)[i] = ((const float4*)Qp)[i];

    float mrow[4], lrow[4], O[4][4];
#pragma unroll
    for (int i = 0; i < 4; i++) {
        mrow[i] = -1e30f;
        lrow[i] = 0.f;
#pragma unroll
        for (int j = 0; j < 4; j++) O[i][j] = 0.f;
    }

    for (int k0 = 0; k0 < Ss; k0 += 64) {
        __syncthreads();  // protect Ks/Vs from previous iteration's readers
        // Load K tile into Ks [64][68]
        for (int i = tid; i < 64 * 16; i += 256) {
            const int r = i >> 4;
            const int c = (i & 15) << 2;
            *(float4*)&Ks[r * KS_LD + c] =
                *(const float4*)&Kp[(size_t)(k0 + r) * DHh + c];
        }
        // Load V tile into Vs [64][64]
        for (int i = tid; i < 1024; i += 256)
            ((float4*)Vs)[i] = ((const float4*)(Vp + (size_t)k0 * DHh))[i];
        __syncthreads();

        // Scores: s[i][j] = Qs[row] . Ks[col]
        float s[4][4];
#pragma unroll
        for (int i = 0; i < 4; i++)
#pragma unroll
            for (int j = 0; j < 4; j++) s[i][j] = 0.f;

#pragma unroll
        for (int d = 0; d < DHh; d += 4) {
            float4 a[4], bb[4];
#pragma unroll
            for (int i = 0; i < 4; i++)
                a[i] = *(const float4*)&Qs[(ty + 16 * i) * DHh + d];
#pragma unroll
            for (int j = 0; j < 4; j++)
                bb[j] = *(const float4*)&Ks[(tx + 16 * j) * KS_LD + d];
#pragma unroll
            for (int i = 0; i < 4; i++)
#pragma unroll
                for (int j = 0; j < 4; j++)
                    s[i][j] += a[i].x * bb[j].x + a[i].y * bb[j].y +
                               a[i].z * bb[j].z + a[i].w * bb[j].w;
        }

        // Mask + online softmax update
#pragma unroll
        for (int i = 0; i < 4; i++) {
            const int qrow = q0 + ty + 16 * i;
            const float* mp = mask + (size_t)qrow * Ss + k0;
#pragma unroll
            for (int j = 0; j < 4; j++) s[i][j] += mp[tx + 16 * j];

            float mt = fmaxf(fmaxf(s[i][0], s[i][1]), fmaxf(s[i][2], s[i][3]));
#pragma unroll
            for (int off = 8; off; off >>= 1)
                mt = fmaxf(mt, __shfl_xor_sync(0xffffffffu, mt, off));
            const float mn = fmaxf(mrow[i], mt);
            const float sc = __expf(mrow[i] - mn);
            float lt = 0.f;
#pragma unroll
            for (int j = 0; j < 4; j++) {
                s[i][j] = __expf(s[i][j] - mn);
                lt += s[i][j];
            }
#pragma unroll
            for (int off = 8; off; off >>= 1)
                lt += __shfl_xor_sync(0xffffffffu, lt, off);
            lrow[i] = lrow[i] * sc + lt;
            mrow[i] = mn;
#pragma unroll
            for (int j = 0; j < 4; j++) O[i][j] *= sc;
        }

        __syncthreads();  // everyone done reading Ks
        // Stage P into Ks buffer
#pragma unroll
        for (int i = 0; i < 4; i++)
#pragma unroll
            for (int j = 0; j < 4; j++)
                Ks[(ty + 16 * i) * KS_LD + tx + 16 * j] = s[i][j];
        __syncthreads();

        // O += P @ V  (O cols = tx*4+j, vectorized V loads)
#pragma unroll
        for (int k = 0; k < 64; k += 4) {
            float4 p4[4];
#pragma unroll
            for (int i = 0; i < 4; i++)
                p4[i] = *(const float4*)&Ks[(ty + 16 * i) * KS_LD + k];
            float pf[4][4];
#pragma unroll
            for (int i = 0; i < 4; i++) {
                pf[i][0] = p4[i].x; pf[i][1] = p4[i].y;
                pf[i][2] = p4[i].z; pf[i][3] = p4[i].w;
            }
#pragma unroll
            for (int kk = 0; kk < 4; kk++) {
                const float4 v = *(const float4*)&Vs[(k + kk) * DHh + tx * 4];
#pragma unroll
                for (int i = 0; i < 4; i++) {
                    O[i][0] += pf[i][kk] * v.x;
                    O[i][1] += pf[i][kk] * v.y;
                    O[i][2] += pf[i][kk] * v.z;
                    O[i][3] += pf[i][kk] * v.w;
                }
            }
        }
    }

    // Epilogue: normalize and store to AO [B,S,D]
#pragma unroll
    for (int i = 0; i < 4; i++) {
        const float inv = 1.0f / lrow[i];
        const int qrow = q0 + ty + 16 * i;
        float4 r = make_float4(O[i][0] * inv, O[i][1] * inv,
                               O[i][2] * inv, O[i][3] * inv);
        *(float4*)&AO[((size_t)(b * Ss + qrow)) * Dd + h * DHh + tx * 4] = r;
    }
}

// ---------------------------------------------------------------------------
extern "C" void kernel_launch(void* const* d_in, const int* in_sizes, int n_in,
                              void* d_out, int out_size)
{
    (void)in_sizes; (void)n_in; (void)out_size;
    const float* seq  = (const float*)d_in[0];
    const float* mask = (const float*)d_in[1];
    const float* Wq   = (const float*)d_in[2];
    const float* bq   = (const float*)d_in[3];
    const float* Wk   = (const float*)d_in[4];
    const float* bk   = (const float*)d_in[5];
    const float* Wv   = (const float*)d_in[6];
    const float* bv   = (const float*)d_in[7];
    const float* Wo   = (const float*)d_in[8];
    const float* bo   = (const float*)d_in[9];
    float* out = (float*)d_out;

    float *Qg, *Kg, *Vg, *AOg;
    cudaGetSymbolAddress((void**)&Qg,  g_Q);
    cudaGetSymbolAddress((void**)&Kg,  g_K);
    cudaGetSymbolAddress((void**)&Vg,  g_V);
    cudaGetSymbolAddress((void**)&AOg, g_AO);

    cudaFuncSetAttribute(flash_attn,
                         cudaFuncAttributeMaxDynamicSharedMemorySize,
                         FLASH_SMEM);

    const dim3 blk(256);
    const dim3 gemm_grid(Dd / 128, (Bb * Ss) / 128);   // (6, 64)

    // QKV projections (SCALE folded into Q)
    sgemm_bias<<<gemm_grid, blk>>>(seq, Wq, bq, Qg, 0.125f, 0);
    sgemm_bias<<<gemm_grid, blk>>>(seq, Wk, bk, Kg, 1.0f, 0);
    sgemm_bias<<<gemm_grid, blk>>>(seq, Wv, bv, Vg, 1.0f, 0);

    // Fused attention
    flash_attn<<<dim3(Ss / 64, Bb * Hh), blk, FLASH_SMEM>>>(Qg, Kg, Vg, mask, AOg);

    // Output projection -> d_out [B,S,D] row-major
    sgemm_bias<<<gemm_grid, blk>>>(AOg, Wo, bo, out, 1.0f, 1);
}

// round 2
// speedup vs baseline: 2.5099x; 2.5099x over previous
#include <cuda_runtime.h>
#include <stdint.h>
#include <math.h>

// Problem constants
#define Bb  2
#define Ss  4096
#define Dd  768
#define Hh  12
#define DHh 64

// Scratch (device globals — no allocation allowed)
__device__ float g_Q[(size_t)Bb * Hh * Ss * DHh];   // [B,H,S,DH], pre-scaled
__device__ float g_K[(size_t)Bb * Hh * Ss * DHh];
__device__ float g_V[(size_t)Bb * Hh * Ss * DHh];
__device__ float g_AO[(size_t)Bb * Ss * Dd];

// ---------------------------------------------------------------------------
// tf32 MMA helpers (mma.sync.m16n8k8.row.col.f32.tf32.tf32.f32)
// ---------------------------------------------------------------------------
__device__ __forceinline__ float cvt_tf32_f(float x) {
    uint32_t u;
    asm("cvt.rna.tf32.f32 %0, %1;" : "=r"(u) : "f"(x));
    return __uint_as_float(u);
}
__device__ __forceinline__ uint32_t sptr(const void* p) {
    return (uint32_t)__cvta_generic_to_shared(p);
}
__device__ __forceinline__ void ldsm4(uint32_t a, uint32_t* r) {
    asm volatile("ldmatrix.sync.aligned.m8n8.x4.shared.b16 {%0,%1,%2,%3}, [%4];"
                 : "=r"(r[0]), "=r"(r[1]), "=r"(r[2]), "=r"(r[3]) : "r"(a));
}
__device__ __forceinline__ void ldsm2(uint32_t a, uint32_t* r) {
    asm volatile("ldmatrix.sync.aligned.m8n8.x2.shared.b16 {%0,%1}, [%2];"
                 : "=r"(r[0]), "=r"(r[1]) : "r"(a));
}
__device__ __forceinline__ void mma8(float* d, const uint32_t* a, const uint32_t* b) {
    asm volatile("mma.sync.aligned.m16n8k8.row.col.f32.tf32.tf32.f32 "
                 "{%0,%1,%2,%3}, {%4,%5,%6,%7}, {%8,%9}, {%0,%1,%2,%3};"
                 : "+f"(d[0]), "+f"(d[1]), "+f"(d[2]), "+f"(d[3])
                 : "r"(a[0]), "r"(a[1]), "r"(a[2]), "r"(a[3]),
                   "r"(b[0]), "r"(b[1]));
}

// ---------------------------------------------------------------------------
// tf32 tensor-core GEMM: out = alpha * (X @ W^T + bias)
//   X: [M,768] row-major, W: [N,768] row-major, bias: [N]
//   mode 0: scatter to [B,H,S,DH]   mode 1: row-major [M,768]
// BM=128, BN=128, BK=32; 8 warps (2x4); warp tile 64x32.
// ---------------------------------------------------------------------------
#define XS_LD 36

__global__ void __launch_bounds__(256) gemm_tf32(
    const float* __restrict__ X, const float* __restrict__ W,
    const float* __restrict__ bias, float* __restrict__ out,
    float alpha, int mode)
{
    __shared__ float Xs[128 * XS_LD];
    __shared__ float Ws[128 * XS_LD];

    const int tid = threadIdx.x, lane = tid & 31, wp = tid >> 5;
    const int m0 = blockIdx.y * 128, n0 = blockIdx.x * 128;
    const int wm = (wp >> 2) * 64, wn = (wp & 3) * 32;

    int ldrow[4], ldc[4];
#pragma unroll
    for (int c = 0; c < 4; c++) {
        int idx = c * 256 + tid;
        ldrow[c] = idx >> 3;
        ldc[c] = (idx & 7) * 4;
    }

    const float* Xg = X + (size_t)m0 * Dd;
    const float* Wg = W + (size_t)n0 * Dd;

    float4 xb[4], wb[4];
#pragma unroll
    for (int c = 0; c < 4; c++) {
        xb[c] = *(const float4*)(Xg + (size_t)ldrow[c] * Dd + ldc[c]);
        wb[c] = *(const float4*)(Wg + (size_t)ldrow[c] * Dd + ldc[c]);
    }

    float acc[4][4][4];
#pragma unroll
    for (int i = 0; i < 4; i++)
#pragma unroll
        for (int j = 0; j < 4; j++)
#pragma unroll
            for (int r = 0; r < 4; r++) acc[i][j][r] = 0.f;

    const int rA = (lane & 7) + ((lane & 8) ? 8 : 0);
    const int cA = (lane & 16) ? 4 : 0;
    const int rB = lane & 7;
    const int cB = (lane & 8) ? 4 : 0;
    const uint32_t xsb = sptr(Xs) + (uint32_t)(((wm + rA) * XS_LD + cA) * 4);
    const uint32_t wsb = sptr(Ws) + (uint32_t)(((wn + rB) * XS_LD + cB) * 4);

    for (int k0 = 0; k0 < Dd; k0 += 32) {
        __syncthreads();
#pragma unroll
        for (int c = 0; c < 4; c++) {
            *(float4*)&Xs[ldrow[c] * XS_LD + ldc[c]] =
                make_float4(cvt_tf32_f(xb[c].x), cvt_tf32_f(xb[c].y),
                            cvt_tf32_f(xb[c].z), cvt_tf32_f(xb[c].w));
            *(float4*)&Ws[ldrow[c] * XS_LD + ldc[c]] =
                make_float4(cvt_tf32_f(wb[c].x), cvt_tf32_f(wb[c].y),
                            cvt_tf32_f(wb[c].z), cvt_tf32_f(wb[c].w));
        }
        __syncthreads();
        if (k0 + 32 < Dd) {
#pragma unroll
            for (int c = 0; c < 4; c++) {
                xb[c] = *(const float4*)(Xg + (size_t)ldrow[c] * Dd + k0 + 32 + ldc[c]);
                wb[c] = *(const float4*)(Wg + (size_t)ldrow[c] * Dd + k0 + 32 + ldc[c]);
            }
        }
#pragma unroll
        for (int s = 0; s < 4; s++) {
            uint32_t af[4][4];
#pragma unroll
            for (int i = 0; i < 4; i++)
                ldsm4(xsb + (uint32_t)((16 * i * XS_LD + 8 * s) * 4), af[i]);
#pragma unroll
            for (int j = 0; j < 4; j++) {
                uint32_t bf[2];
                ldsm2(wsb + (uint32_t)((8 * j * XS_LD + 8 * s) * 4), bf);
#pragma unroll
                for (int i = 0; i < 4; i++) mma8(acc[i][j], af[i], bf);
            }
        }
    }

    // Epilogue
    const int mr = m0 + wm + (lane >> 2);
    const int nc = n0 + wn + 2 * (lane & 3);
#pragma unroll
    for (int j = 0; j < 4; j++) {
        const int n = nc + 8 * j;
        const float bv0 = bias[n], bv1 = bias[n + 1];
#pragma unroll
        for (int i = 0; i < 4; i++) {
            const int m = mr + 16 * i;
            float2 r0 = make_float2(alpha * (acc[i][j][0] + bv0),
                                    alpha * (acc[i][j][1] + bv1));
            float2 r1 = make_float2(alpha * (acc[i][j][2] + bv0),
                                    alpha * (acc[i][j][3] + bv1));
            if (mode == 0) {
                const int bb = m >> 12, ss = m & 4095, hh = n >> 6, dh = n & 63;
                float* p = out + ((size_t)(bb * Hh + hh) * Ss + ss) * DHh + dh;
                *(float2*)p = r0;
                *(float2*)(p + 8 * DHh) = r1;
            } else {
                float* p = out + (size_t)m * Dd + n;
                *(float2*)p = r0;
                *(float2*)(p + 8 * Dd) = r1;
            }
        }
    }
}

// ---------------------------------------------------------------------------
// Flash attention with tf32 tensor cores.
// grid (32, 24), block 256 (8 warps). Q tile 128 rows (16/warp, frags resident),
// KV tiles of 64. Online softmax on C-fragments; P via smem round-trip
// (warp-private rows -> __syncwarp only). Next K/V tile prefetched in regs.
// ---------------------------------------------------------------------------
#define SLD 68
#define FSM ((128 + 64 + 64) * SLD * 4)

__global__ void __launch_bounds__(256) flash_tc(
    const float* __restrict__ Q, const float* __restrict__ K,
    const float* __restrict__ V, const float* __restrict__ mask,
    float* __restrict__ AO)
{
    extern __shared__ float sm[];
    float* Ps = sm;                    // [128][SLD], also Qs at init
    float* Ks = sm + 128 * SLD;        // [64][SLD]
    float* Vt = Ks + 64 * SLD;         // [64(dh)][SLD] transposed V

    const int tid = threadIdx.x, lane = tid & 31, wp = tid >> 5;
    const int q0 = blockIdx.x * 128;
    const int bh = blockIdx.y;
    const int b = bh / Hh, h = bh - b * Hh;

    const float* Qp = Q + ((size_t)bh * Ss + q0) * DHh;
    const float* Kp = K + (size_t)bh * Ss * DHh;
    const float* Vp = V + (size_t)bh * Ss * DHh;

    // Stage Q tile (tf32-rounded)
    for (int i = tid; i < 128 * 16; i += 256) {
        const int r = i >> 4, c = (i & 15) * 4;
        float4 v = *(const float4*)(Qp + (size_t)r * DHh + c);
        *(float4*)&Ps[r * SLD + c] =
            make_float4(cvt_tf32_f(v.x), cvt_tf32_f(v.y),
                        cvt_tf32_f(v.z), cvt_tf32_f(v.w));
    }
    __syncthreads();

    const int rA = (lane & 7) + ((lane & 8) ? 8 : 0);
    const int cA = (lane & 16) ? 4 : 0;
    const int rB = lane & 7;
    const int cB = (lane & 8) ? 4 : 0;

    // Q fragments, resident for whole KV loop
    uint32_t qf[8][4];
    {
        const uint32_t qb = sptr(Ps) + (uint32_t)(((16 * wp + rA) * SLD + cA) * 4);
#pragma unroll
        for (int s = 0; s < 8; s++) ldsm4(qb + (uint32_t)(8 * s * 4), qf[s]);
    }

    float O[8][4];
#pragma unroll
    for (int j = 0; j < 8; j++)
#pragma unroll
        for (int r = 0; r < 4; r++) O[j][r] = 0.f;
    float mr0 = -1e30f, mr1 = -1e30f, lr0 = 0.f, lr1 = 0.f;

    // K load mapping (coalesced), V load mapping (row-strided for conflict-free
    // transposed STS)
    int krow[4], kc[4], vrow[4], vc[4];
#pragma unroll
    for (int c = 0; c < 4; c++) {
        int idx = c * 256 + tid;
        krow[c] = idx >> 4;  kc[c] = (idx & 15) * 4;
        vrow[c] = idx & 63;  vc[c] = (idx >> 6) * 4;
    }

    float4 kb[4], vb[4];
#pragma unroll
    for (int c = 0; c < 4; c++) {
        kb[c] = *(const float4*)(Kp + (size_t)krow[c] * DHh + kc[c]);
        vb[c] = *(const float4*)(Vp + (size_t)vrow[c] * DHh + vc[c]);
    }

    const uint32_t ksb = sptr(Ks) + (uint32_t)((rB * SLD + cB) * 4);
    const uint32_t vtb = sptr(Vt) + (uint32_t)((rB * SLD + cB) * 4);
    const uint32_t psb = sptr(Ps) + (uint32_t)(((16 * wp + rA) * SLD + cA) * 4);

    const int prow = 16 * wp + (lane >> 2);
    const int pcol = 2 * (lane & 3);
    const float* mbase = mask + (size_t)(q0 + prow) * Ss + pcol;

    for (int kt = 0; kt < Ss / 64; kt++) {
        __syncthreads();
        // Stage K (tf32)
#pragma unroll
        for (int c = 0; c < 4; c++)
            *(float4*)&Ks[krow[c] * SLD + kc[c]] =
                make_float4(cvt_tf32_f(kb[c].x), cvt_tf32_f(kb[c].y),
                            cvt_tf32_f(kb[c].z), cvt_tf32_f(kb[c].w));
        // Stage V transposed: Vt[dh][kv]
#pragma unroll
        for (int c = 0; c < 4; c++) {
            Vt[(vc[c] + 0) * SLD + vrow[c]] = cvt_tf32_f(vb[c].x);
            Vt[(vc[c] + 1) * SLD + vrow[c]] = cvt_tf32_f(vb[c].y);
            Vt[(vc[c] + 2) * SLD + vrow[c]] = cvt_tf32_f(vb[c].z);
            Vt[(vc[c] + 3) * SLD + vrow[c]] = cvt_tf32_f(vb[c].w);
        }
        __syncthreads();

        // Prefetch next K/V tile
        if (kt + 1 < Ss / 64) {
            const float* Kn = Kp + (size_t)(kt + 1) * 64 * DHh;
            const float* Vn = Vp + (size_t)(kt + 1) * 64 * DHh;
#pragma unroll
            for (int c = 0; c < 4; c++) {
                kb[c] = *(const float4*)(Kn + (size_t)krow[c] * DHh + kc[c]);
                vb[c] = *(const float4*)(Vn + (size_t)vrow[c] * DHh + vc[c]);
            }
        }

        // Scores: S = Q @ K^T   (per warp: 16 x 64)
        float sc[8][4];
#pragma unroll
        for (int j = 0; j < 8; j++)
#pragma unroll
            for (int r = 0; r < 4; r++) sc[j][r] = 0.f;
#pragma unroll
        for (int s = 0; s < 8; s++) {
#pragma unroll
            for (int j = 0; j < 8; j++) {
                uint32_t bf[2];
                ldsm2(ksb + (uint32_t)((8 * j * SLD + 8 * s) * 4), bf);
                mma8(sc[j], qf[s], bf);
            }
        }

        // Mask add
        const float* mp = mbase + kt * 64;
#pragma unroll
        for (int j = 0; j < 8; j++) {
            float2 m0v = *(const float2*)(mp + 8 * j);
            float2 m1v = *(const float2*)(mp + 8 * (size_t)Ss + 8 * j);
            sc[j][0] += m0v.x; sc[j][1] += m0v.y;
            sc[j][2] += m1v.x; sc[j][3] += m1v.y;
        }

        // Online softmax (rows prow, prow+8)
        float mx0 = -1e30f, mx1 = -1e30f;
#pragma unroll
        for (int j = 0; j < 8; j++) {
            mx0 = fmaxf(mx0, fmaxf(sc[j][0], sc[j][1]));
            mx1 = fmaxf(mx1, fmaxf(sc[j][2], sc[j][3]));
        }
        mx0 = fmaxf(mx0, __shfl_xor_sync(0xffffffffu, mx0, 1));
        mx0 = fmaxf(mx0, __shfl_xor_sync(0xffffffffu, mx0, 2));
        mx1 = fmaxf(mx1, __shfl_xor_sync(0xffffffffu, mx1, 1));
        mx1 = fmaxf(mx1, __shfl_xor_sync(0xffffffffu, mx1, 2));
        const float mn0 = fmaxf(mr0, mx0), mn1 = fmaxf(mr1, mx1);
        const float s0 = __expf(mr0 - mn0), s1 = __expf(mr1 - mn1);
        float sum0 = 0.f, sum1 = 0.f;
#pragma unroll
        for (int j = 0; j < 8; j++) {
            sc[j][0] = __expf(sc[j][0] - mn0); sum0 += sc[j][0];
            sc[j][1] = __expf(sc[j][1] - mn0); sum0 += sc[j][1];
            sc[j][2] = __expf(sc[j][2] - mn1); sum1 += sc[j][2];
            sc[j][3] = __expf(sc[j][3] - mn1); sum1 += sc[j][3];
        }
        sum0 += __shfl_xor_sync(0xffffffffu, sum0, 1);
        sum0 += __shfl_xor_sync(0xffffffffu, sum0, 2);
        sum1 += __shfl_xor_sync(0xffffffffu, sum1, 1);
        sum1 += __shfl_xor_sync(0xffffffffu, sum1, 2);
        lr0 = lr0 * s0 + sum0; lr1 = lr1 * s1 + sum1;
        mr0 = mn0; mr1 = mn1;
#pragma unroll
        for (int j = 0; j < 8; j++) {
            O[j][0] *= s0; O[j][1] *= s0;
            O[j][2] *= s1; O[j][3] *= s1;
        }

        // P -> smem (warp-private rows), tf32-rounded
        float* Pp0 = &Ps[prow * SLD + pcol];
        float* Pp1 = &Ps[(prow + 8) * SLD + pcol];
#pragma unroll
        for (int j = 0; j < 8; j++) {
            Pp0[8 * j] = cvt_tf32_f(sc[j][0]); Pp0[8 * j + 1] = cvt_tf32_f(sc[j][1]);
            Pp1[8 * j] = cvt_tf32_f(sc[j][2]); Pp1[8 * j + 1] = cvt_tf32_f(sc[j][3]);
        }
        __syncwarp();

        // O += P @ V
        uint32_t pf[8][4];
#pragma unroll
        for (int s = 0; s < 8; s++) ldsm4(psb + (uint32_t)(8 * s * 4), pf[s]);
#pragma unroll
        for (int s = 0; s < 8; s++) {
#pragma unroll
            for (int j = 0; j < 8; j++) {
                uint32_t bf[2];
                ldsm2(vtb + (uint32_t)((8 * j * SLD + 8 * s) * 4), bf);
                mma8(O[j], pf[s], bf);
            }
        }
    }

    // Epilogue: normalize and scatter to AO [B,S,D]
    const float i0 = 1.f / lr0, i1 = 1.f / lr1;
    float* Op = AO + ((size_t)b * Ss + q0 + prow) * Dd + h * DHh + pcol;
#pragma unroll
    for (int j = 0; j < 8; j++) {
        *(float2*)(Op + 8 * j) = make_float2(O[j][0] * i0, O[j][1] * i0);
        *(float2*)(Op + 8 * (size_t)Dd + 8 * j) = make_float2(O[j][2] * i1, O[j][3] * i1);
    }
}

// ---------------------------------------------------------------------------
extern "C" void kernel_launch(void* const* d_in, const int* in_sizes, int n_in,
                              void* d_out, int out_size)
{
    (void)in_sizes; (void)n_in; (void)out_size;
    const float* seq  = (const float*)d_in[0];
    const float* mask = (const float*)d_in[1];
    const float* Wq   = (const float*)d_in[2];
    const float* bq   = (const float*)d_in[3];
    const float* Wk   = (const float*)d_in[4];
    const float* bk   = (const float*)d_in[5];
    const float* Wv   = (const float*)d_in[6];
    const float* bv   = (const float*)d_in[7];
    const float* Wo   = (const float*)d_in[8];
    const float* bo   = (const float*)d_in[9];
    float* out = (float*)d_out;

    float *Qg, *Kg, *Vg, *AOg;
    cudaGetSymbolAddress((void**)&Qg,  g_Q);
    cudaGetSymbolAddress((void**)&Kg,  g_K);
    cudaGetSymbolAddress((void**)&Vg,  g_V);
    cudaGetSymbolAddress((void**)&AOg, g_AO);

    cudaFuncSetAttribute(flash_tc,
                         cudaFuncAttributeMaxDynamicSharedMemorySize, FSM);

    const dim3 blk(256);
    const dim3 gemm_grid(Dd / 128, (Bb * Ss) / 128);   // (6, 64)

    // QKV projections (SCALE folded into Q)
    gemm_tf32<<<gemm_grid, blk>>>(seq, Wq, bq, Qg, 0.125f, 0);
    gemm_tf32<<<gemm_grid, blk>>>(seq, Wk, bk, Kg, 1.0f, 0);
    gemm_tf32<<<gemm_grid, blk>>>(seq, Wv, bv, Vg, 1.0f, 0);

    // Fused flash attention
    flash_tc<<<dim3(Ss / 128, Bb * Hh), blk, FSM>>>(Qg, Kg, Vg, mask, AOg);

    // Output projection
    gemm_tf32<<<gemm_grid, blk>>>(AOg, Wo, bo, out, 1.0f, 1);
}

// round 3
// speedup vs baseline: 3.3419x; 1.3315x over previous
#include <cuda_runtime.h>
#include <cuda_fp16.h>
#include <stdint.h>
#include <math.h>

// Problem constants
#define Bb  2
#define Ss  4096
#define Dd  768
#define Hh  12
#define DHh 64

// Scratch (device globals)
__device__ __half g_Q[(size_t)Bb * Hh * Ss * DHh];
__device__ __half g_K[(size_t)Bb * Hh * Ss * DHh];
__device__ __half g_V[(size_t)Bb * Hh * Ss * DHh];
__device__ __half g_AO[(size_t)Bb * Ss * Dd];

// ---------------------------------------------------------------------------
__device__ __forceinline__ uint32_t sptr(const void* p) {
    return (uint32_t)__cvta_generic_to_shared(p);
}
__device__ __forceinline__ void ldsm4(uint32_t a, uint32_t* r) {
    asm volatile("ldmatrix.sync.aligned.m8n8.x4.shared.b16 {%0,%1,%2,%3}, [%4];"
                 : "=r"(r[0]), "=r"(r[1]), "=r"(r[2]), "=r"(r[3]) : "r"(a));
}
__device__ __forceinline__ void ldsm4t(uint32_t a, uint32_t* r) {
    asm volatile("ldmatrix.sync.aligned.m8n8.x4.trans.shared.b16 {%0,%1,%2,%3}, [%4];"
                 : "=r"(r[0]), "=r"(r[1]), "=r"(r[2]), "=r"(r[3]) : "r"(a));
}
// D(f32) += A(f16) * B(f16) ; m16n8k16
__device__ __forceinline__ void mma16(float* d, const uint32_t* a, const uint32_t* b) {
    asm volatile("mma.sync.aligned.m16n8k16.row.col.f32.f16.f16.f32 "
                 "{%0,%1,%2,%3}, {%4,%5,%6,%7}, {%8,%9}, {%0,%1,%2,%3};"
                 : "+f"(d[0]), "+f"(d[1]), "+f"(d[2]), "+f"(d[3])
                 : "r"(a[0]), "r"(a[1]), "r"(a[2]), "r"(a[3]),
                   "r"(b[0]), "r"(b[1]));
}
__device__ __forceinline__ uint32_t pack2(float x, float y) {
    __half2 h = __floats2half2_rn(x, y);
    return *(uint32_t*)&h;
}

// ---------------------------------------------------------------------------
// fp16 tensor-core GEMM: out = alpha * (X @ W^T + bias)
//   X: [M,768] float (Xf) or half (Xh); W: [N,768] float; bias: [N] float
//   mode 0: half out scattered to [B,H,S,DH]; mode 1: float out [M,768]
// BM=128, BN=128, BK=32; 8 warps, warp tile 64x32.
// ---------------------------------------------------------------------------
#define GLD 40

__global__ void __launch_bounds__(256) gemm_f16(
    const float* __restrict__ Xf, const __half* __restrict__ Xh,
    const float* __restrict__ W, const float* __restrict__ bias,
    float* __restrict__ outf, __half* __restrict__ outh,
    float alpha, int mode)
{
    __shared__ __half Xs[128 * GLD];
    __shared__ __half Ws[128 * GLD];

    const int tid = threadIdx.x, lane = tid & 31, wp = tid >> 5;
    const int m0 = blockIdx.y * 128, n0 = blockIdx.x * 128;
    const int wm = (wp >> 2) * 64, wn = (wp & 3) * 32;
    const bool xhalf = (Xh != nullptr);

    // load mappings
    int frow[4], fcol[4];           // float path: 4 floats per chunk
#pragma unroll
    for (int c = 0; c < 4; c++) {
        int idx = c * 256 + tid;
        frow[c] = idx >> 3; fcol[c] = (idx & 7) * 4;
    }
    int hrow[2], hcol[2];           // half path: 8 halves per chunk
#pragma unroll
    for (int c = 0; c < 2; c++) {
        int idx = c * 256 + tid;
        hrow[c] = idx >> 2; hcol[c] = (idx & 3) * 8;
    }

    const float*  Wg  = W + (size_t)n0 * Dd;
    const float*  Xgf = xhalf ? nullptr : Xf + (size_t)m0 * Dd;
    const __half* Xgh = xhalf ? Xh + (size_t)m0 * Dd : nullptr;

    float4 wb[4], xbf[4];
    uint4 xbh[2];
#pragma unroll
    for (int c = 0; c < 4; c++)
        wb[c] = *(const float4*)(Wg + (size_t)frow[c] * Dd + fcol[c]);
    if (xhalf) {
#pragma unroll
        for (int c = 0; c < 2; c++)
            xbh[c] = *(const uint4*)(Xgh + (size_t)hrow[c] * Dd + hcol[c]);
    } else {
#pragma unroll
        for (int c = 0; c < 4; c++)
            xbf[c] = *(const float4*)(Xgf + (size_t)frow[c] * Dd + fcol[c]);
    }

    float acc[4][4][4];
#pragma unroll
    for (int i = 0; i < 4; i++)
#pragma unroll
        for (int j = 0; j < 4; j++)
#pragma unroll
            for (int r = 0; r < 4; r++) acc[i][j][r] = 0.f;

    // ldmatrix addresses
    const int arow = wm + (lane & 15);
    const int acol = (lane & 16) ? 8 : 0;
    const uint32_t xsb = sptr(Xs) + (uint32_t)((arow * GLD + acol) * 2);
    const int brow0 = wn + (lane & 7) + ((lane & 16) ? 8 : 0);
    const int bcol  = (lane & 8) ? 8 : 0;
    const uint32_t wsb = sptr(Ws) + (uint32_t)((brow0 * GLD + bcol) * 2);

    for (int k0 = 0; k0 < Dd; k0 += 32) {
        __syncthreads();
#pragma unroll
        for (int c = 0; c < 4; c++) {
            uint32_t lo = pack2(wb[c].x, wb[c].y);
            uint32_t hi = pack2(wb[c].z, wb[c].w);
            *(uint2*)&Ws[frow[c] * GLD + fcol[c]] = make_uint2(lo, hi);
        }
        if (xhalf) {
#pragma unroll
            for (int c = 0; c < 2; c++) {
                *(uint2*)&Xs[hrow[c] * GLD + hcol[c]] =
                    make_uint2(xbh[c].x, xbh[c].y);
                *(uint2*)&Xs[hrow[c] * GLD + hcol[c] + 4] =
                    make_uint2(xbh[c].z, xbh[c].w);
            }
        } else {
#pragma unroll
            for (int c = 0; c < 4; c++) {
                uint32_t lo = pack2(xbf[c].x, xbf[c].y);
                uint32_t hi = pack2(xbf[c].z, xbf[c].w);
                *(uint2*)&Xs[frow[c] * GLD + fcol[c]] = make_uint2(lo, hi);
            }
        }
        __syncthreads();

        if (k0 + 32 < Dd) {
#pragma unroll
            for (int c = 0; c < 4; c++)
                wb[c] = *(const float4*)(Wg + (size_t)frow[c] * Dd + k0 + 32 + fcol[c]);
            if (xhalf) {
#pragma unroll
                for (int c = 0; c < 2; c++)
                    xbh[c] = *(const uint4*)(Xgh + (size_t)hrow[c] * Dd + k0 + 32 + hcol[c]);
            } else {
#pragma unroll
                for (int c = 0; c < 4; c++)
                    xbf[c] = *(const float4*)(Xgf + (size_t)frow[c] * Dd + k0 + 32 + fcol[c]);
            }
        }

#pragma unroll
        for (int s = 0; s < 2; s++) {        // two k16 chunks
            uint32_t af[4][4];
#pragma unroll
            for (int i = 0; i < 4; i++)
                ldsm4(xsb + (uint32_t)((16 * i * GLD + 16 * s) * 2), af[i]);
#pragma unroll
            for (int g = 0; g < 2; g++) {    // 2 n16 groups -> 4 n8 tiles
                uint32_t bf[4];
                ldsm4(wsb + (uint32_t)((16 * g * GLD + 16 * s) * 2), bf);
#pragma unroll
                for (int i = 0; i < 4; i++) {
                    mma16(acc[i][2 * g],     af[i], bf);
                    mma16(acc[i][2 * g + 1], af[i], bf + 2);
                }
            }
        }
    }

    // Epilogue
    const int mr = m0 + wm + (lane >> 2);
    const int nc = n0 + wn + 2 * (lane & 3);
#pragma unroll
    for (int j = 0; j < 4; j++) {
        const int n = nc + 8 * j;
        const float bv0 = bias[n], bv1 = bias[n + 1];
#pragma unroll
        for (int i = 0; i < 4; i++) {
            const int m = mr + 16 * i;
            const float r00 = alpha * (acc[i][j][0] + bv0);
            const float r01 = alpha * (acc[i][j][1] + bv1);
            const float r10 = alpha * (acc[i][j][2] + bv0);
            const float r11 = alpha * (acc[i][j][3] + bv1);
            if (mode == 0) {
                const int bb = m >> 12, ss = m & 4095, hh = n >> 6, dh = n & 63;
                __half* p = outh + ((size_t)(bb * Hh + hh) * Ss + ss) * DHh + dh;
                *(__half2*)p = __floats2half2_rn(r00, r01);
                *(__half2*)(p + 8 * DHh) = __floats2half2_rn(r10, r11);
            } else {
                float* p = outf + (size_t)m * Dd + n;
                *(float2*)p = make_float2(r00, r01);
                *(float2*)(p + 8 * Dd) = make_float2(r10, r11);
            }
        }
    }
}

// ---------------------------------------------------------------------------
// fp16 flash attention. grid (32, 24), block 256 (8 warps).
// Q tile 128 rows (16/warp, A-frags resident); 64-row KV tiles.
// P stays in registers (C-frag -> A-frag repack). V row-major + ldmatrix.trans.
// ---------------------------------------------------------------------------
#define KLD 72
// smem: Q staging uses whole region [128][KLD]; then K=[64][KLD], V=[64][KLD]

__global__ void __launch_bounds__(256) flash_f16(
    const __half* __restrict__ Q, const __half* __restrict__ K,
    const __half* __restrict__ V, const float* __restrict__ mask,
    __half* __restrict__ AO)
{
    __shared__ __half sm[128 * KLD];
    __half* Ks = sm;
    __half* Vs = sm + 64 * KLD;

    const int tid = threadIdx.x, lane = tid & 31, wp = tid >> 5;
    const int q0 = blockIdx.x * 128;
    const int bh = blockIdx.y;
    const int b = bh / Hh, h = bh - b * Hh;

    const __half* Qp = Q + ((size_t)bh * Ss + q0) * DHh;
    const __half* Kp = K + (size_t)bh * Ss * DHh;
    const __half* Vp = V + (size_t)bh * Ss * DHh;

    // ---- Stage Q tile [128][64] and load A-fragments ----
    {
        for (int c = 0; c < 4; c++) {
            int idx = c * 256 + tid;
            int r = idx >> 3, ch = (idx & 7) * 8;
            *(uint4*)&sm[r * KLD + ch] = *(const uint4*)(Qp + (size_t)r * DHh + ch);
        }
    }
    __syncthreads();

    uint32_t qf[4][4];
    {
        const uint32_t qb = sptr(sm) +
            (uint32_t)(((16 * wp + (lane & 15)) * KLD + ((lane & 16) ? 8 : 0)) * 2);
#pragma unroll
        for (int s = 0; s < 4; s++) ldsm4(qb + (uint32_t)(16 * s * 2), qf[s]);
    }
    __syncthreads();

    float O[8][4];
#pragma unroll
    for (int j = 0; j < 8; j++)
#pragma unroll
        for (int r = 0; r < 4; r++) O[j][r] = 0.f;
    float mr0 = -1e30f, mr1 = -1e30f, lr0 = 0.f, lr1 = 0.f;

    // staging maps: 64x64 halves, 2 chunks of uint4 per thread
    int srow[2], scol[2];
#pragma unroll
    for (int c = 0; c < 2; c++) {
        int idx = c * 256 + tid;
        srow[c] = idx >> 3; scol[c] = (idx & 7) * 8;
    }

    uint4 kb[2], vb[2];
#pragma unroll
    for (int c = 0; c < 2; c++) {
        kb[c] = *(const uint4*)(Kp + (size_t)srow[c] * DHh + scol[c]);
        vb[c] = *(const uint4*)(Vp + (size_t)srow[c] * DHh + scol[c]);
    }

    // ldmatrix bases
    const int krow = (lane & 7) + ((lane & 16) ? 8 : 0);
    const int kcol = (lane & 8) ? 8 : 0;
    const uint32_t ksb = sptr(Ks) + (uint32_t)((krow * KLD + kcol) * 2);
    const int vrow = lane & 15;
    const int vcol = (lane & 16) ? 8 : 0;
    const uint32_t vsb = sptr(Vs) + (uint32_t)((vrow * KLD + vcol) * 2);

    const int prow = 16 * wp + (lane >> 2);
    const int pcol = 2 * (lane & 3);
    const float* mbase = mask + (size_t)(q0 + prow) * Ss + pcol;

    for (int kt = 0; kt < Ss / 64; kt++) {
        __syncthreads();
#pragma unroll
        for (int c = 0; c < 2; c++) {
            *(uint4*)&Ks[srow[c] * KLD + scol[c]] = kb[c];
            *(uint4*)&Vs[srow[c] * KLD + scol[c]] = vb[c];
        }
        __syncthreads();

        if (kt + 1 < Ss / 64) {
            const __half* Kn = Kp + (size_t)(kt + 1) * 64 * DHh;
            const __half* Vn = Vp + (size_t)(kt + 1) * 64 * DHh;
#pragma unroll
            for (int c = 0; c < 2; c++) {
                kb[c] = *(const uint4*)(Kn + (size_t)srow[c] * DHh + scol[c]);
                vb[c] = *(const uint4*)(Vn + (size_t)srow[c] * DHh + scol[c]);
            }
        }

        // ---- Scores: per warp 16 x 64 ----
        float sc[8][4];
#pragma unroll
        for (int j = 0; j < 8; j++)
#pragma unroll
            for (int r = 0; r < 4; r++) sc[j][r] = 0.f;
#pragma unroll
        for (int s = 0; s < 4; s++) {       // k16 chunks over dh
#pragma unroll
            for (int g = 0; g < 4; g++) {   // n16 groups over kv
                uint32_t bf[4];
                ldsm4(ksb + (uint32_t)((16 * g * KLD + 16 * s) * 2), bf);
                mma16(sc[2 * g],     qf[s], bf);
                mma16(sc[2 * g + 1], qf[s], bf + 2);
            }
        }

        // ---- Mask add ----
        const float* mp = mbase + kt * 64;
#pragma unroll
        for (int j = 0; j < 8; j++) {
            float2 m0v = *(const float2*)(mp + 8 * j);
            float2 m1v = *(const float2*)(mp + 8 * (size_t)Ss + 8 * j);
            sc[j][0] += m0v.x; sc[j][1] += m0v.y;
            sc[j][2] += m1v.x; sc[j][3] += m1v.y;
        }

        // ---- Online softmax ----
        float mx0 = -1e30f, mx1 = -1e30f;
#pragma unroll
        for (int j = 0; j < 8; j++) {
            mx0 = fmaxf(mx0, fmaxf(sc[j][0], sc[j][1]));
            mx1 = fmaxf(mx1, fmaxf(sc[j][2], sc[j][3]));
        }
        mx0 = fmaxf(mx0, __shfl_xor_sync(0xffffffffu, mx0, 1));
        mx0 = fmaxf(mx0, __shfl_xor_sync(0xffffffffu, mx0, 2));
        mx1 = fmaxf(mx1, __shfl_xor_sync(0xffffffffu, mx1, 1));
        mx1 = fmaxf(mx1, __shfl_xor_sync(0xffffffffu, mx1, 2));
        const float mn0 = fmaxf(mr0, mx0), mn1 = fmaxf(mr1, mx1);
        const float s0 = __expf(mr0 - mn0), s1 = __expf(mr1 - mn1);
        float sum0 = 0.f, sum1 = 0.f;
#pragma unroll
        for (int j = 0; j < 8; j++) {
            sc[j][0] = __expf(sc[j][0] - mn0); sum0 += sc[j][0];
            sc[j][1] = __expf(sc[j][1] - mn0); sum0 += sc[j][1];
            sc[j][2] = __expf(sc[j][2] - mn1); sum1 += sc[j][2];
            sc[j][3] = __expf(sc[j][3] - mn1); sum1 += sc[j][3];
        }
        sum0 += __shfl_xor_sync(0xffffffffu, sum0, 1);
        sum0 += __shfl_xor_sync(0xffffffffu, sum0, 2);
        sum1 += __shfl_xor_sync(0xffffffffu, sum1, 1);
        sum1 += __shfl_xor_sync(0xffffffffu, sum1, 2);
        lr0 = lr0 * s0 + sum0; lr1 = lr1 * s1 + sum1;
        mr0 = mn0; mr1 = mn1;
#pragma unroll
        for (int j = 0; j < 8; j++) {
            O[j][0] *= s0; O[j][1] *= s0;
            O[j][2] *= s1; O[j][3] *= s1;
        }

        // ---- P: C-frag -> A-frag repack (registers only) ----
        uint32_t pf[4][4];
#pragma unroll
        for (int s = 0; s < 4; s++) {
            pf[s][0] = pack2(sc[2 * s][0],     sc[2 * s][1]);
            pf[s][1] = pack2(sc[2 * s][2],     sc[2 * s][3]);
            pf[s][2] = pack2(sc[2 * s + 1][0], sc[2 * s + 1][1]);
            pf[s][3] = pack2(sc[2 * s + 1][2], sc[2 * s + 1][3]);
        }

        // ---- O += P @ V ----
#pragma unroll
        for (int s = 0; s < 4; s++) {       // k16 chunks over kv
#pragma unroll
            for (int g = 0; g < 4; g++) {   // n16 groups over dh
                uint32_t bf[4];
                ldsm4t(vsb + (uint32_t)((16 * s * KLD + 16 * g) * 2), bf);
                mma16(O[2 * g],     pf[s], bf);
                mma16(O[2 * g + 1], pf[s], bf + 2);
            }
        }
    }

    // ---- Epilogue: normalize, write AO (half) [B,S,D] ----
    const float i0 = 1.f / lr0, i1 = 1.f / lr1;
    __half* Op = AO + ((size_t)b * Ss + q0 + prow) * Dd + h * DHh + pcol;
#pragma unroll
    for (int j = 0; j < 8; j++) {
        *(__half2*)(Op + 8 * j) = __floats2half2_rn(O[j][0] * i0, O[j][1] * i0);
        *(__half2*)(Op + 8 * (size_t)Dd + 8 * j) =
            __floats2half2_rn(O[j][2] * i1, O[j][3] * i1);
    }
}

// ---------------------------------------------------------------------------
extern "C" void kernel_launch(void* const* d_in, const int* in_sizes, int n_in,
                              void* d_out, int out_size)
{
    (void)in_sizes; (void)n_in; (void)out_size;
    const float* seq  = (const float*)d_in[0];
    const float* mask = (const float*)d_in[1];
    const float* Wq   = (const float*)d_in[2];
    const float* bq   = (const float*)d_in[3];
    const float* Wk   = (const float*)d_in[4];
    const float* bk   = (const float*)d_in[5];
    const float* Wv   = (const float*)d_in[6];
    const float* bv   = (const float*)d_in[7];
    const float* Wo   = (const float*)d_in[8];
    const float* bo   = (const float*)d_in[9];
    float* out = (float*)d_out;

    __half *Qg, *Kg, *Vg, *AOg;
    cudaGetSymbolAddress((void**)&Qg,  g_Q);
    cudaGetSymbolAddress((void**)&Kg,  g_K);
    cudaGetSymbolAddress((void**)&Vg,  g_V);
    cudaGetSymbolAddress((void**)&AOg, g_AO);

    const dim3 blk(256);
    const dim3 gemm_grid(Dd / 128, (Bb * Ss) / 128);   // (6, 64)

    gemm_f16<<<gemm_grid, blk>>>(seq, nullptr, Wq, bq, nullptr, Qg, 0.125f, 0);
    gemm_f16<<<gemm_grid, blk>>>(seq, nullptr, Wk, bk, nullptr, Kg, 1.0f, 0);
    gemm_f16<<<gemm_grid, blk>>>(seq, nullptr, Wv, bv, nullptr, Vg, 1.0f, 0);

    flash_f16<<<dim3(Ss / 128, Bb * Hh), blk>>>(Qg, Kg, Vg, mask, AOg);

    gemm_f16<<<gemm_grid, blk>>>(nullptr, AOg, Wo, bo, out, nullptr, 1.0f, 1);
}

// round 4
// speedup vs baseline: 5.6856x; 1.7013x over previous
#include <cuda_runtime.h>
#include <cuda_fp16.h>
#include <stdint.h>
#include <math.h>

// Problem constants
#define Bb  2
#define Ss  4096
#define Dd  768
#define Hh  12
#define DHh 64

// Scratch (device globals)
__device__ __half g_Q[(size_t)Bb * Hh * Ss * DHh];
__device__ __half g_K[(size_t)Bb * Hh * Ss * DHh];
__device__ __half g_V[(size_t)Bb * Hh * Ss * DHh];
__device__ __half g_AO[(size_t)Bb * Ss * Dd];

// ---------------------------------------------------------------------------
__device__ __forceinline__ uint32_t sptr(const void* p) {
    return (uint32_t)__cvta_generic_to_shared(p);
}
__device__ __forceinline__ void ldsm4(uint32_t a, uint32_t* r) {
    asm volatile("ldmatrix.sync.aligned.m8n8.x4.shared.b16 {%0,%1,%2,%3}, [%4];"
                 : "=r"(r[0]), "=r"(r[1]), "=r"(r[2]), "=r"(r[3]) : "r"(a));
}
__device__ __forceinline__ void ldsm4t(uint32_t a, uint32_t* r) {
    asm volatile("ldmatrix.sync.aligned.m8n8.x4.trans.shared.b16 {%0,%1,%2,%3}, [%4];"
                 : "=r"(r[0]), "=r"(r[1]), "=r"(r[2]), "=r"(r[3]) : "r"(a));
}
__device__ __forceinline__ void mma16(float* d, const uint32_t* a, const uint32_t* b) {
    asm volatile("mma.sync.aligned.m16n8k16.row.col.f32.f16.f16.f32 "
                 "{%0,%1,%2,%3}, {%4,%5,%6,%7}, {%8,%9}, {%0,%1,%2,%3};"
                 : "+f"(d[0]), "+f"(d[1]), "+f"(d[2]), "+f"(d[3])
                 : "r"(a[0]), "r"(a[1]), "r"(a[2]), "r"(a[3]),
                   "r"(b[0]), "r"(b[1]));
}
__device__ __forceinline__ uint32_t pack2(float x, float y) {
    __half2 h = __floats2half2_rn(x, y);
    return *(uint32_t*)&h;
}
__device__ __forceinline__ void cp16(uint32_t s, const void* g) {
    asm volatile("cp.async.cg.shared.global [%0], [%1], 16;" :: "r"(s), "l"(g));
}
#define CP_COMMIT() asm volatile("cp.async.commit_group;")
#define CP_WAIT1()  asm volatile("cp.async.wait_group 1;")

// ---------------------------------------------------------------------------
// fp16 tensor-core GEMM (unchanged from R3): out = alpha * (X @ W^T + bias)
// ---------------------------------------------------------------------------
#define GLD 40

__global__ void __launch_bounds__(256) gemm_f16(
    const float* __restrict__ Xf, const __half* __restrict__ Xh,
    const float* __restrict__ W, const float* __restrict__ bias,
    float* __restrict__ outf, __half* __restrict__ outh,
    float alpha, int mode)
{
    __shared__ __half Xs[128 * GLD];
    __shared__ __half Ws[128 * GLD];

    const int tid = threadIdx.x, lane = tid & 31, wp = tid >> 5;
    const int m0 = blockIdx.y * 128, n0 = blockIdx.x * 128;
    const int wm = (wp >> 2) * 64, wn = (wp & 3) * 32;
    const bool xhalf = (Xh != nullptr);

    int frow[4], fcol[4];
#pragma unroll
    for (int c = 0; c < 4; c++) {
        int idx = c * 256 + tid;
        frow[c] = idx >> 3; fcol[c] = (idx & 7) * 4;
    }
    int hrow[2], hcol[2];
#pragma unroll
    for (int c = 0; c < 2; c++) {
        int idx = c * 256 + tid;
        hrow[c] = idx >> 2; hcol[c] = (idx & 3) * 8;
    }

    const float*  Wg  = W + (size_t)n0 * Dd;
    const float*  Xgf = xhalf ? nullptr : Xf + (size_t)m0 * Dd;
    const __half* Xgh = xhalf ? Xh + (size_t)m0 * Dd : nullptr;

    float4 wb[4], xbf[4];
    uint4 xbh[2];
#pragma unroll
    for (int c = 0; c < 4; c++)
        wb[c] = *(const float4*)(Wg + (size_t)frow[c] * Dd + fcol[c]);
    if (xhalf) {
#pragma unroll
        for (int c = 0; c < 2; c++)
            xbh[c] = *(const uint4*)(Xgh + (size_t)hrow[c] * Dd + hcol[c]);
    } else {
#pragma unroll
        for (int c = 0; c < 4; c++)
            xbf[c] = *(const float4*)(Xgf + (size_t)frow[c] * Dd + fcol[c]);
    }

    float acc[4][4][4];
#pragma unroll
    for (int i = 0; i < 4; i++)
#pragma unroll
        for (int j = 0; j < 4; j++)
#pragma unroll
            for (int r = 0; r < 4; r++) acc[i][j][r] = 0.f;

    const int arow = wm + (lane & 15);
    const int acol = (lane & 16) ? 8 : 0;
    const uint32_t xsb = sptr(Xs) + (uint32_t)((arow * GLD + acol) * 2);
    const int brow0 = wn + (lane & 7) + ((lane & 16) ? 8 : 0);
    const int bcol  = (lane & 8) ? 8 : 0;
    const uint32_t wsb = sptr(Ws) + (uint32_t)((brow0 * GLD + bcol) * 2);

    for (int k0 = 0; k0 < Dd; k0 += 32) {
        __syncthreads();
#pragma unroll
        for (int c = 0; c < 4; c++) {
            uint32_t lo = pack2(wb[c].x, wb[c].y);
            uint32_t hi = pack2(wb[c].z, wb[c].w);
            *(uint2*)&Ws[frow[c] * GLD + fcol[c]] = make_uint2(lo, hi);
        }
        if (xhalf) {
#pragma unroll
            for (int c = 0; c < 2; c++) {
                *(uint2*)&Xs[hrow[c] * GLD + hcol[c]] =
                    make_uint2(xbh[c].x, xbh[c].y);
                *(uint2*)&Xs[hrow[c] * GLD + hcol[c] + 4] =
                    make_uint2(xbh[c].z, xbh[c].w);
            }
        } else {
#pragma unroll
            for (int c = 0; c < 4; c++) {
                uint32_t lo = pack2(xbf[c].x, xbf[c].y);
                uint32_t hi = pack2(xbf[c].z, xbf[c].w);
                *(uint2*)&Xs[frow[c] * GLD + fcol[c]] = make_uint2(lo, hi);
            }
        }
        __syncthreads();

        if (k0 + 32 < Dd) {
#pragma unroll
            for (int c = 0; c < 4; c++)
                wb[c] = *(const float4*)(Wg + (size_t)frow[c] * Dd + k0 + 32 + fcol[c]);
            if (xhalf) {
#pragma unroll
                for (int c = 0; c < 2; c++)
                    xbh[c] = *(const uint4*)(Xgh + (size_t)hrow[c] * Dd + k0 + 32 + hcol[c]);
            } else {
#pragma unroll
                for (int c = 0; c < 4; c++)
                    xbf[c] = *(const float4*)(Xgf + (size_t)frow[c] * Dd + k0 + 32 + fcol[c]);
            }
        }

#pragma unroll
        for (int s = 0; s < 2; s++) {
            uint32_t af[4][4];
#pragma unroll
            for (int i = 0; i < 4; i++)
                ldsm4(xsb + (uint32_t)((16 * i * GLD + 16 * s) * 2), af[i]);
#pragma unroll
            for (int g = 0; g < 2; g++) {
                uint32_t bf[4];
                ldsm4(wsb + (uint32_t)((16 * g * GLD + 16 * s) * 2), bf);
#pragma unroll
                for (int i = 0; i < 4; i++) {
                    mma16(acc[i][2 * g],     af[i], bf);
                    mma16(acc[i][2 * g + 1], af[i], bf + 2);
                }
            }
        }
    }

    const int mr = m0 + wm + (lane >> 2);
    const int nc = n0 + wn + 2 * (lane & 3);
#pragma unroll
    for (int j = 0; j < 4; j++) {
        const int n = nc + 8 * j;
        const float bv0 = bias[n], bv1 = bias[n + 1];
#pragma unroll
        for (int i = 0; i < 4; i++) {
            const int m = mr + 16 * i;
            const float r00 = alpha * (acc[i][j][0] + bv0);
            const float r01 = alpha * (acc[i][j][1] + bv1);
            const float r10 = alpha * (acc[i][j][2] + bv0);
            const float r11 = alpha * (acc[i][j][3] + bv1);
            if (mode == 0) {
                const int bb = m >> 12, ss = m & 4095, hh = n >> 6, dh = n & 63;
                __half* p = outh + ((size_t)(bb * Hh + hh) * Ss + ss) * DHh + dh;
                *(__half2*)p = __floats2half2_rn(r00, r01);
                *(__half2*)(p + 8 * DHh) = __floats2half2_rn(r10, r11);
            } else {
                float* p = outf + (size_t)m * Dd + n;
                *(float2*)p = make_float2(r00, r01);
                *(float2*)(p + 8 * Dd) = make_float2(r10, r11);
            }
        }
    }
}

// ---------------------------------------------------------------------------
// fp16 flash attention, 2 CTAs/SM, cp.async double-buffered K/V.
// grid (32, 24), block 256 (8 warps). Q tile 128 rows (16/warp, frags resident);
// 64-row KV tiles. P stays in registers (C->A repack).
// ---------------------------------------------------------------------------
#define KLD 72
#define TILE_H (64 * KLD)          // halves per 64-row tile buffer

__global__ void __launch_bounds__(256, 2) flash_f16(
    const __half* __restrict__ Q, const __half* __restrict__ K,
    const __half* __restrict__ V, const float* __restrict__ mask,
    __half* __restrict__ AO)
{
    __shared__ __half sm[2][2][TILE_H];   // [stage][K/V][tile]

    const int tid = threadIdx.x, lane = tid & 31, wp = tid >> 5;
    const int q0 = blockIdx.x * 128;
    const int bh = blockIdx.y;
    const int b = bh / Hh, h = bh - b * Hh;

    const __half* Qp = Q + ((size_t)bh * Ss + q0) * DHh;
    const __half* Kp = K + (size_t)bh * Ss * DHh;
    const __half* Vp = V + (size_t)bh * Ss * DHh;

    // ---- Stage Q tile [128][64] into sm[0] region, load A-frags ----
    {
        __half* qstage = &sm[0][0][0];
#pragma unroll
        for (int c = 0; c < 4; c++) {
            int idx = c * 256 + tid;
            int r = idx >> 3, ch = (idx & 7) * 8;
            *(uint4*)&qstage[r * KLD + ch] = *(const uint4*)(Qp + (size_t)r * DHh + ch);
        }
    }
    __syncthreads();

    uint32_t qf[4][4];
    {
        const uint32_t qb = sptr(&sm[0][0][0]) +
            (uint32_t)(((16 * wp + (lane & 15)) * KLD + ((lane & 16) ? 8 : 0)) * 2);
#pragma unroll
        for (int s = 0; s < 4; s++) ldsm4(qb + (uint32_t)(16 * s * 2), qf[s]);
    }
    __syncthreads();

    // staging map: 64x64 halves, 2 x 16B per thread per tensor
    int srow[2], scol[2];
#pragma unroll
    for (int c = 0; c < 2; c++) {
        int idx = c * 256 + tid;
        srow[c] = idx >> 3; scol[c] = (idx & 7) * 8;
    }
    uint32_t kdst[2][2], vdst[2][2];
#pragma unroll
    for (int st = 0; st < 2; st++)
#pragma unroll
        for (int c = 0; c < 2; c++) {
            kdst[st][c] = sptr(&sm[st][0][srow[c] * KLD + scol[c]]);
            vdst[st][c] = sptr(&sm[st][1][srow[c] * KLD + scol[c]]);
        }

    // ldmatrix bases per stage
    const int krow = (lane & 7) + ((lane & 16) ? 8 : 0);
    const int kcol = (lane & 8) ? 8 : 0;
    const int vrow = lane & 15;
    const int vcol = (lane & 16) ? 8 : 0;
    uint32_t ksb[2], vsb[2];
#pragma unroll
    for (int st = 0; st < 2; st++) {
        ksb[st] = sptr(&sm[st][0][0]) + (uint32_t)((krow * KLD + kcol) * 2);
        vsb[st] = sptr(&sm[st][1][0]) + (uint32_t)((vrow * KLD + vcol) * 2);
    }

    float O[8][4];
#pragma unroll
    for (int j = 0; j < 8; j++)
#pragma unroll
        for (int r = 0; r < 4; r++) O[j][r] = 0.f;
    float mr0 = -1e30f, mr1 = -1e30f, lr0 = 0.f, lr1 = 0.f;

    const int prow = 16 * wp + (lane >> 2);
    const int pcol = 2 * (lane & 3);
    const float* mbase = mask + (size_t)(q0 + prow) * Ss + pcol;

    const int NT = Ss / 64;

    // preload tile 0 into stage 0
#pragma unroll
    for (int c = 0; c < 2; c++) {
        cp16(kdst[0][c], Kp + (size_t)srow[c] * DHh + scol[c]);
        cp16(vdst[0][c], Vp + (size_t)srow[c] * DHh + scol[c]);
    }
    CP_COMMIT();

    for (int kt = 0; kt < NT; kt++) {
        const int cur = kt & 1;
        // prefetch next tile (empty group on last iter keeps wait semantics)
        if (kt + 1 < NT) {
            const __half* Kn = Kp + (size_t)(kt + 1) * 64 * DHh;
            const __half* Vn = Vp + (size_t)(kt + 1) * 64 * DHh;
#pragma unroll
            for (int c = 0; c < 2; c++) {
                cp16(kdst[cur ^ 1][c], Kn + (size_t)srow[c] * DHh + scol[c]);
                cp16(vdst[cur ^ 1][c], Vn + (size_t)srow[c] * DHh + scol[c]);
            }
        }
        CP_COMMIT();
        CP_WAIT1();
        __syncthreads();

        // ---- Scores: per warp 16 x 64, pipelined ldsm/mma ----
        float sc[8][4];
#pragma unroll
        for (int j = 0; j < 8; j++)
#pragma unroll
            for (int r = 0; r < 4; r++) sc[j][r] = 0.f;

        {
            uint32_t bf[2][4];
            ldsm4(ksb[cur], bf[0]);   // s=0,g=0
#pragma unroll
            for (int i = 0; i < 16; i++) {      // i = s*4 + g
                const int s = i >> 2, g = i & 3;
                if (i + 1 < 16) {
                    const int s2 = (i + 1) >> 2, g2 = (i + 1) & 3;
                    ldsm4(ksb[cur] + (uint32_t)((16 * g2 * KLD + 16 * s2) * 2),
                          bf[(i + 1) & 1]);
                }
                mma16(sc[2 * g],     qf[s], bf[i & 1]);
                mma16(sc[2 * g + 1], qf[s], bf[i & 1] + 2);
            }
        }

        // ---- Mask add ----
        const float* mp = mbase + kt * 64;
#pragma unroll
        for (int j = 0; j < 8; j++) {
            float2 m0v = *(const float2*)(mp + 8 * j);
            float2 m1v = *(const float2*)(mp + 8 * (size_t)Ss + 8 * j);
            sc[j][0] += m0v.x; sc[j][1] += m0v.y;
            sc[j][2] += m1v.x; sc[j][3] += m1v.y;
        }

        // ---- Online softmax ----
        float mx0 = -1e30f, mx1 = -1e30f;
#pragma unroll
        for (int j = 0; j < 8; j++) {
            mx0 = fmaxf(mx0, fmaxf(sc[j][0], sc[j][1]));
            mx1 = fmaxf(mx1, fmaxf(sc[j][2], sc[j][3]));
        }
        mx0 = fmaxf(mx0, __shfl_xor_sync(0xffffffffu, mx0, 1));
        mx0 = fmaxf(mx0, __shfl_xor_sync(0xffffffffu, mx0, 2));
        mx1 = fmaxf(mx1, __shfl_xor_sync(0xffffffffu, mx1, 1));
        mx1 = fmaxf(mx1, __shfl_xor_sync(0xffffffffu, mx1, 2));
        const float mn0 = fmaxf(mr0, mx0), mn1 = fmaxf(mr1, mx1);
        const float s0 = __expf(mr0 - mn0), s1 = __expf(mr1 - mn1);
        float sum0 = 0.f, sum1 = 0.f;
#pragma unroll
        for (int j = 0; j < 8; j++) {
            sc[j][0] = __expf(sc[j][0] - mn0); sum0 += sc[j][0];
            sc[j][1] = __expf(sc[j][1] - mn0); sum0 += sc[j][1];
            sc[j][2] = __expf(sc[j][2] - mn1); sum1 += sc[j][2];
            sc[j][3] = __expf(sc[j][3] - mn1); sum1 += sc[j][3];
        }
        sum0 += __shfl_xor_sync(0xffffffffu, sum0, 1);
        sum0 += __shfl_xor_sync(0xffffffffu, sum0, 2);
        sum1 += __shfl_xor_sync(0xffffffffu, sum1, 1);
        sum1 += __shfl_xor_sync(0xffffffffu, sum1, 2);
        lr0 = lr0 * s0 + sum0; lr1 = lr1 * s1 + sum1;
        mr0 = mn0; mr1 = mn1;
#pragma unroll
        for (int j = 0; j < 8; j++) {
            O[j][0] *= s0; O[j][1] *= s0;
            O[j][2] *= s1; O[j][3] *= s1;
        }

        // ---- P: C-frag -> A-frag repack ----
        uint32_t pf[4][4];
#pragma unroll
        for (int s = 0; s < 4; s++) {
            pf[s][0] = pack2(sc[2 * s][0],     sc[2 * s][1]);
            pf[s][1] = pack2(sc[2 * s][2],     sc[2 * s][3]);
            pf[s][2] = pack2(sc[2 * s + 1][0], sc[2 * s + 1][1]);
            pf[s][3] = pack2(sc[2 * s + 1][2], sc[2 * s + 1][3]);
        }

        // ---- O += P @ V, pipelined ldsm/mma ----
        {
            uint32_t bf[2][4];
            ldsm4t(vsb[cur], bf[0]);  // s=0,g=0
#pragma unroll
            for (int i = 0; i < 16; i++) {      // i = s*4 + g
                const int s = i >> 2, g = i & 3;
                if (i + 1 < 16) {
                    const int s2 = (i + 1) >> 2, g2 = (i + 1) & 3;
                    ldsm4t(vsb[cur] + (uint32_t)((16 * s2 * KLD + 16 * g2) * 2),
                           bf[(i + 1) & 1]);
                }
                mma16(O[2 * g],     pf[s], bf[i & 1]);
                mma16(O[2 * g + 1], pf[s], bf[i & 1] + 2);
            }
        }
        __syncthreads();   // all reads of stage `cur` done before next prefetch
    }

    // ---- Epilogue: normalize, write AO (half) [B,S,D] ----
    const float i0 = 1.f / lr0, i1 = 1.f / lr1;
    __half* Op = AO + ((size_t)b * Ss + q0 + prow) * Dd + h * DHh + pcol;
#pragma unroll
    for (int j = 0; j < 8; j++) {
        *(__half2*)(Op + 8 * j) = __floats2half2_rn(O[j][0] * i0, O[j][1] * i0);
        *(__half2*)(Op + 8 * (size_t)Dd + 8 * j) =
            __floats2half2_rn(O[j][2] * i1, O[j][3] * i1);
    }
}

// ---------------------------------------------------------------------------
extern "C" void kernel_launch(void* const* d_in, const int* in_sizes, int n_in,
                              void* d_out, int out_size)
{
    (void)in_sizes; (void)n_in; (void)out_size;
    const float* seq  = (const float*)d_in[0];
    const float* mask = (const float*)d_in[1];
    const float* Wq   = (const float*)d_in[2];
    const float* bq   = (const float*)d_in[3];
    const float* Wk   = (const float*)d_in[4];
    const float* bk   = (const float*)d_in[5];
    const float* Wv   = (const float*)d_in[6];
    const float* bv   = (const float*)d_in[7];
    const float* Wo   = (const float*)d_in[8];
    const float* bo   = (const float*)d_in[9];
    float* out = (float*)d_out;

    __half *Qg, *Kg, *Vg, *AOg;
    cudaGetSymbolAddress((void**)&Qg,  g_Q);
    cudaGetSymbolAddress((void**)&Kg,  g_K);
    cudaGetSymbolAddress((void**)&Vg,  g_V);
    cudaGetSymbolAddress((void**)&AOg, g_AO);

    const dim3 blk(256);
    const dim3 gemm_grid(Dd / 128, (Bb * Ss) / 128);   // (6, 64)

    gemm_f16<<<gemm_grid, blk>>>(seq, nullptr, Wq, bq, nullptr, Qg, 0.125f, 0);
    gemm_f16<<<gemm_grid, blk>>>(seq, nullptr, Wk, bk, nullptr, Kg, 1.0f, 0);
    gemm_f16<<<gemm_grid, blk>>>(seq, nullptr, Wv, bv, nullptr, Vg, 1.0f, 0);

    flash_f16<<<dim3(Ss / 128, Bb * Hh), blk>>>(Qg, Kg, Vg, mask, AOg);

    gemm_f16<<<gemm_grid, blk>>>(nullptr, AOg, Wo, bo, out, nullptr, 1.0f, 1);
}

// round 6
// speedup vs baseline: 6.1699x; 1.0852x over previous
#include <cuda_runtime.h>
#include <cuda_fp16.h>
#include <stdint.h>
#include <math.h>

// Problem constants
#define Bb  2
#define Ss  4096
#define Dd  768
#define Hh  12
#define DHh 64

#define LOG2E 1.44269504088896341f

// Scratch (device globals)
__device__ __half g_Q[(size_t)Bb * Hh * Ss * DHh];
__device__ __half g_K[(size_t)Bb * Hh * Ss * DHh];
__device__ __half g_V[(size_t)Bb * Hh * Ss * DHh];
__device__ __half g_AO[(size_t)Bb * Ss * Dd];

// ---------------------------------------------------------------------------
__device__ __forceinline__ uint32_t sptr(const void* p) {
    return (uint32_t)__cvta_generic_to_shared(p);
}
__device__ __forceinline__ void ldsm4(uint32_t a, uint32_t* r) {
    asm volatile("ldmatrix.sync.aligned.m8n8.x4.shared.b16 {%0,%1,%2,%3}, [%4];"
                 : "=r"(r[0]), "=r"(r[1]), "=r"(r[2]), "=r"(r[3]) : "r"(a));
}
__device__ __forceinline__ void ldsm4t(uint32_t a, uint32_t* r) {
    asm volatile("ldmatrix.sync.aligned.m8n8.x4.trans.shared.b16 {%0,%1,%2,%3}, [%4];"
                 : "=r"(r[0]), "=r"(r[1]), "=r"(r[2]), "=r"(r[3]) : "r"(a));
}
__device__ __forceinline__ void mma16(float* d, const uint32_t* a, const uint32_t* b) {
    asm volatile("mma.sync.aligned.m16n8k16.row.col.f32.f16.f16.f32 "
                 "{%0,%1,%2,%3}, {%4,%5,%6,%7}, {%8,%9}, {%0,%1,%2,%3};"
                 : "+f"(d[0]), "+f"(d[1]), "+f"(d[2]), "+f"(d[3])
                 : "r"(a[0]), "r"(a[1]), "r"(a[2]), "r"(a[3]),
                   "r"(b[0]), "r"(b[1]));
}
__device__ __forceinline__ uint32_t pack2(float x, float y) {
    __half2 h = __floats2half2_rn(x, y);
    return *(uint32_t*)&h;
}
__device__ __forceinline__ void cp16(uint32_t s, const void* g) {
    asm volatile("cp.async.cg.shared.global [%0], [%1], 16;" :: "r"(s), "l"(g));
}
#define CP_COMMIT() asm volatile("cp.async.commit_group;")
#define CP_WAIT1()  asm volatile("cp.async.wait_group 1;")

// ---------------------------------------------------------------------------
// fp16 tensor-core GEMM: out = alpha * (X @ W^T + bias)
//   Identical math to R4 (proven). mode 0: half out -> [B,H,S,DH];
//   mode 1: float out [M,768].
// ---------------------------------------------------------------------------
#define GLD 40

__device__ __forceinline__ void gemm_f16_body(
    const float* __restrict__ Xf, const __half* __restrict__ Xh,
    const float* __restrict__ W, const float* __restrict__ bias,
    float* __restrict__ outf, __half* __restrict__ outh,
    float alpha, int mode, int m0, int n0,
    __half* Xs, __half* Ws)
{
    const int tid = threadIdx.x, lane = tid & 31, wp = tid >> 5;
    const int wm = (wp >> 2) * 64, wn = (wp & 3) * 32;
    const bool xhalf = (Xh != nullptr);

    int frow[4], fcol[4];
#pragma unroll
    for (int c = 0; c < 4; c++) {
        int idx = c * 256 + tid;
        frow[c] = idx >> 3; fcol[c] = (idx & 7) * 4;
    }
    int hrow[2], hcol[2];
#pragma unroll
    for (int c = 0; c < 2; c++) {
        int idx = c * 256 + tid;
        hrow[c] = idx >> 2; hcol[c] = (idx & 3) * 8;
    }

    const float*  Wg  = W + (size_t)n0 * Dd;
    const float*  Xgf = xhalf ? nullptr : Xf + (size_t)m0 * Dd;
    const __half* Xgh = xhalf ? Xh + (size_t)m0 * Dd : nullptr;

    float4 wb[4], xbf[4];
    uint4 xbh[2];
#pragma unroll
    for (int c = 0; c < 4; c++)
        wb[c] = *(const float4*)(Wg + (size_t)frow[c] * Dd + fcol[c]);
    if (xhalf) {
#pragma unroll
        for (int c = 0; c < 2; c++)
            xbh[c] = *(const uint4*)(Xgh + (size_t)hrow[c] * Dd + hcol[c]);
    } else {
#pragma unroll
        for (int c = 0; c < 4; c++)
            xbf[c] = *(const float4*)(Xgf + (size_t)frow[c] * Dd + fcol[c]);
    }

    float acc[4][4][4];
#pragma unroll
    for (int i = 0; i < 4; i++)
#pragma unroll
        for (int j = 0; j < 4; j++)
#pragma unroll
            for (int r = 0; r < 4; r++) acc[i][j][r] = 0.f;

    const int arow = wm + (lane & 15);
    const int acol = (lane & 16) ? 8 : 0;
    const uint32_t xsb = sptr(Xs) + (uint32_t)((arow * GLD + acol) * 2);
    const int brow0 = wn + (lane & 7) + ((lane & 16) ? 8 : 0);
    const int bcol  = (lane & 8) ? 8 : 0;
    const uint32_t wsb = sptr(Ws) + (uint32_t)((brow0 * GLD + bcol) * 2);

    for (int k0 = 0; k0 < Dd; k0 += 32) {
        __syncthreads();
#pragma unroll
        for (int c = 0; c < 4; c++) {
            uint32_t lo = pack2(wb[c].x, wb[c].y);
            uint32_t hi = pack2(wb[c].z, wb[c].w);
            *(uint2*)&Ws[frow[c] * GLD + fcol[c]] = make_uint2(lo, hi);
        }
        if (xhalf) {
#pragma unroll
            for (int c = 0; c < 2; c++) {
                *(uint2*)&Xs[hrow[c] * GLD + hcol[c]] =
                    make_uint2(xbh[c].x, xbh[c].y);
                *(uint2*)&Xs[hrow[c] * GLD + hcol[c] + 4] =
                    make_uint2(xbh[c].z, xbh[c].w);
            }
        } else {
#pragma unroll
            for (int c = 0; c < 4; c++) {
                uint32_t lo = pack2(xbf[c].x, xbf[c].y);
                uint32_t hi = pack2(xbf[c].z, xbf[c].w);
                *(uint2*)&Xs[frow[c] * GLD + fcol[c]] = make_uint2(lo, hi);
            }
        }
        __syncthreads();

        if (k0 + 32 < Dd) {
#pragma unroll
            for (int c = 0; c < 4; c++)
                wb[c] = *(const float4*)(Wg + (size_t)frow[c] * Dd + k0 + 32 + fcol[c]);
            if (xhalf) {
#pragma unroll
                for (int c = 0; c < 2; c++)
                    xbh[c] = *(const uint4*)(Xgh + (size_t)hrow[c] * Dd + k0 + 32 + hcol[c]);
            } else {
#pragma unroll
                for (int c = 0; c < 4; c++)
                    xbf[c] = *(const float4*)(Xgf + (size_t)frow[c] * Dd + k0 + 32 + fcol[c]);
            }
        }

#pragma unroll
        for (int s = 0; s < 2; s++) {
            uint32_t af[4][4];
#pragma unroll
            for (int i = 0; i < 4; i++)
                ldsm4(xsb + (uint32_t)((16 * i * GLD + 16 * s) * 2), af[i]);
#pragma unroll
            for (int g = 0; g < 2; g++) {
                uint32_t bf[4];
                ldsm4(wsb + (uint32_t)((16 * g * GLD + 16 * s) * 2), bf);
#pragma unroll
                for (int i = 0; i < 4; i++) {
                    mma16(acc[i][2 * g],     af[i], bf);
                    mma16(acc[i][2 * g + 1], af[i], bf + 2);
                }
            }
        }
    }

    const int mr = m0 + wm + (lane >> 2);
    const int nc = n0 + wn + 2 * (lane & 3);
#pragma unroll
    for (int j = 0; j < 4; j++) {
        const int n = nc + 8 * j;
        const float bv0 = bias[n], bv1 = bias[n + 1];
#pragma unroll
        for (int i = 0; i < 4; i++) {
            const int m = mr + 16 * i;
            const float r00 = alpha * (acc[i][j][0] + bv0);
            const float r01 = alpha * (acc[i][j][1] + bv1);
            const float r10 = alpha * (acc[i][j][2] + bv0);
            const float r11 = alpha * (acc[i][j][3] + bv1);
            if (mode == 0) {
                const int bb = m >> 12, ss = m & 4095, hh = n >> 6, dh = n & 63;
                __half* p = outh + ((size_t)(bb * Hh + hh) * Ss + ss) * DHh + dh;
                *(__half2*)p = __floats2half2_rn(r00, r01);
                *(__half2*)(p + 8 * DHh) = __floats2half2_rn(r10, r11);
            } else {
                float* p = outf + (size_t)m * Dd + n;
                *(float2*)p = make_float2(r00, r01);
                *(float2*)(p + 8 * Dd) = make_float2(r10, r11);
            }
        }
    }
}

// merged QKV: grid.x in [0,18) -> sel = x/6 picks Wq/Wk/Wv
__global__ void __launch_bounds__(256) gemm_qkv(
    const float* __restrict__ X,
    const float* __restrict__ Wq, const float* __restrict__ bq,
    const float* __restrict__ Wk, const float* __restrict__ bk,
    const float* __restrict__ Wv, const float* __restrict__ bv,
    __half* __restrict__ Qo, __half* __restrict__ Ko, __half* __restrict__ Vo)
{
    __shared__ __half Xs[128 * GLD];
    __shared__ __half Ws[128 * GLD];
    const int sel = blockIdx.x / 6;
    const int n0 = (blockIdx.x % 6) * 128;
    const int m0 = blockIdx.y * 128;
    const float* W = (sel == 0) ? Wq : (sel == 1) ? Wk : Wv;
    const float* bias = (sel == 0) ? bq : (sel == 1) ? bk : bv;
    __half* out = (sel == 0) ? Qo : (sel == 1) ? Ko : Vo;
    const float alpha = (sel == 0) ? 0.125f * LOG2E : 1.0f;
    gemm_f16_body(X, nullptr, W, bias, nullptr, out, alpha, 0, m0, n0, Xs, Ws);
}

__global__ void __launch_bounds__(256) gemm_out(
    const __half* __restrict__ X, const float* __restrict__ W,
    const float* __restrict__ bias, float* __restrict__ out)
{
    __shared__ __half Xs[128 * GLD];
    __shared__ __half Ws[128 * GLD];
    gemm_f16_body(nullptr, X, W, bias, out, nullptr, 1.0f, 1,
                  blockIdx.y * 128, blockIdx.x * 128, Xs, Ws);
}

// ---------------------------------------------------------------------------
// fp16 flash attention, FA2 warp layout: 4 warps x 32 Q rows, 2 CTAs/SM.
// cp.async double-buffered 64-row K/V tiles; exp2-domain softmax.
// Each K/V B-fragment feeds 4 MMAs (2 A row-tiles) -> half the LDSM per MMA.
// ---------------------------------------------------------------------------
#define KLD 72
#define TILE_H (64 * KLD)

__global__ void __launch_bounds__(128, 2) flash_f16(
    const __half* __restrict__ Q, const __half* __restrict__ K,
    const __half* __restrict__ V, const float* __restrict__ mask,
    __half* __restrict__ AO)
{
    __shared__ __half sm[2][2][TILE_H];

    const int tid = threadIdx.x, lane = tid & 31, wp = tid >> 5;
    const int q0 = blockIdx.x * 128;
    const int bh = blockIdx.y;
    const int b = bh / Hh, h = bh - b * Hh;

    const __half* Qp = Q + ((size_t)bh * Ss + q0) * DHh;
    const __half* Kp = K + (size_t)bh * Ss * DHh;
    const __half* Vp = V + (size_t)bh * Ss * DHh;

    // ---- Stage Q tile [128][64] (row-major, ld=KLD), load A-frags ----
    {
        __half* qstage = &sm[0][0][0];
#pragma unroll
        for (int c = 0; c < 8; c++) {
            int idx = c * 128 + tid;
            int r = idx >> 3, ch = (idx & 7) * 8;
            *(uint4*)&qstage[r * KLD + ch] = *(const uint4*)(Qp + (size_t)r * DHh + ch);
        }
    }
    __syncthreads();

    // warp wp owns rows [32*wp, 32*wp+32): two 16-row A tiles
    uint32_t qf[2][4][4];
#pragma unroll
    for (int t = 0; t < 2; t++) {
        const uint32_t qb = sptr(&sm[0][0][0]) +
            (uint32_t)(((32 * wp + 16 * t + (lane & 15)) * KLD +
                        ((lane & 16) ? 8 : 0)) * 2);
#pragma unroll
        for (int s = 0; s < 4; s++) ldsm4(qb + (uint32_t)(16 * s * 2), qf[t][s]);
    }
    __syncthreads();

    // staging map: 64x64 halves, 4 x 16B per thread per tensor
    int srow[4], scol[4];
#pragma unroll
    for (int c = 0; c < 4; c++) {
        int idx = c * 128 + tid;
        srow[c] = idx >> 3; scol[c] = (idx & 7) * 8;
    }
    uint32_t kdst[2][4], vdst[2][4];
#pragma unroll
    for (int st = 0; st < 2; st++)
#pragma unroll
        for (int c = 0; c < 4; c++) {
            kdst[st][c] = sptr(&sm[st][0][srow[c] * KLD + scol[c]]);
            vdst[st][c] = sptr(&sm[st][1][srow[c] * KLD + scol[c]]);
        }

    const int krow = (lane & 7) + ((lane & 16) ? 8 : 0);
    const int kcol = (lane & 8) ? 8 : 0;
    const int vrow = lane & 15;
    const int vcol = (lane & 16) ? 8 : 0;
    uint32_t ksb[2], vsb[2];
#pragma unroll
    for (int st = 0; st < 2; st++) {
        ksb[st] = sptr(&sm[st][0][0]) + (uint32_t)((krow * KLD + kcol) * 2);
        vsb[st] = sptr(&sm[st][1][0]) + (uint32_t)((vrow * KLD + vcol) * 2);
    }

    float O[2][8][4];
#pragma unroll
    for (int t = 0; t < 2; t++)
#pragma unroll
        for (int j = 0; j < 8; j++)
#pragma unroll
            for (int r = 0; r < 4; r++) O[t][j][r] = 0.f;
    float mr[2][2] = {{-1e30f, -1e30f}, {-1e30f, -1e30f}};
    float lr[2][2] = {{0.f, 0.f}, {0.f, 0.f}};

    const int pcol = 2 * (lane & 3);
    const float* mbase[2];
#pragma unroll
    for (int t = 0; t < 2; t++)
        mbase[t] = mask + (size_t)(q0 + 32 * wp + 16 * t + (lane >> 2)) * Ss + pcol;

    const int NT = Ss / 64;

    // preload tile 0 into stage 0
#pragma unroll
    for (int c = 0; c < 4; c++) {
        cp16(kdst[0][c], Kp + (size_t)srow[c] * DHh + scol[c]);
        cp16(vdst[0][c], Vp + (size_t)srow[c] * DHh + scol[c]);
    }
    CP_COMMIT();

    for (int kt = 0; kt < NT; kt++) {
        const int cur = kt & 1;
        if (kt + 1 < NT) {
            const __half* Kn = Kp + (size_t)(kt + 1) * 64 * DHh;
            const __half* Vn = Vp + (size_t)(kt + 1) * 64 * DHh;
#pragma unroll
            for (int c = 0; c < 4; c++) {
                cp16(kdst[cur ^ 1][c], Kn + (size_t)srow[c] * DHh + scol[c]);
                cp16(vdst[cur ^ 1][c], Vn + (size_t)srow[c] * DHh + scol[c]);
            }
        }
        CP_COMMIT();
        CP_WAIT1();
        __syncthreads();

        // ---- Scores: per warp 32 x 64, one K-frag feeds 4 MMAs ----
        float sc[2][8][4];
#pragma unroll
        for (int t = 0; t < 2; t++)
#pragma unroll
            for (int j = 0; j < 8; j++)
#pragma unroll
                for (int r = 0; r < 4; r++) sc[t][j][r] = 0.f;

        {
            uint32_t bf[2][4];
            ldsm4(ksb[cur], bf[0]);
#pragma unroll
            for (int i = 0; i < 16; i++) {      // i = s*4 + g
                const int s = i >> 2, g = i & 3;
                if (i + 1 < 16) {
                    const int s2 = (i + 1) >> 2, g2 = (i + 1) & 3;
                    ldsm4(ksb[cur] + (uint32_t)((16 * g2 * KLD + 16 * s2) * 2),
                          bf[(i + 1) & 1]);
                }
                mma16(sc[0][2 * g],     qf[0][s], bf[i & 1]);
                mma16(sc[0][2 * g + 1], qf[0][s], bf[i & 1] + 2);
                mma16(sc[1][2 * g],     qf[1][s], bf[i & 1]);
                mma16(sc[1][2 * g + 1], qf[1][s], bf[i & 1] + 2);
            }
        }

        // ---- Mask (log2 domain) + online softmax, per row tile ----
        uint32_t pf[2][4][4];
#pragma unroll
        for (int t = 0; t < 2; t++) {
            const float* mp = mbase[t] + kt * 64;
#pragma unroll
            for (int j = 0; j < 8; j++) {
                float2 m0v = *(const float2*)(mp + 8 * j);
                float2 m1v = *(const float2*)(mp + 8 * (size_t)Ss + 8 * j);
                sc[t][j][0] = fmaf(m0v.x, LOG2E, sc[t][j][0]);
                sc[t][j][1] = fmaf(m0v.y, LOG2E, sc[t][j][1]);
                sc[t][j][2] = fmaf(m1v.x, LOG2E, sc[t][j][2]);
                sc[t][j][3] = fmaf(m1v.y, LOG2E, sc[t][j][3]);
            }

            float mx0 = -1e30f, mx1 = -1e30f;
#pragma unroll
            for (int j = 0; j < 8; j++) {
                mx0 = fmaxf(mx0, fmaxf(sc[t][j][0], sc[t][j][1]));
                mx1 = fmaxf(mx1, fmaxf(sc[t][j][2], sc[t][j][3]));
            }
            mx0 = fmaxf(mx0, __shfl_xor_sync(0xffffffffu, mx0, 1));
            mx0 = fmaxf(mx0, __shfl_xor_sync(0xffffffffu, mx0, 2));
            mx1 = fmaxf(mx1, __shfl_xor_sync(0xffffffffu, mx1, 1));
            mx1 = fmaxf(mx1, __shfl_xor_sync(0xffffffffu, mx1, 2));
            const float mn0 = fmaxf(mr[t][0], mx0), mn1 = fmaxf(mr[t][1], mx1);
            const float s0 = exp2f(mr[t][0] - mn0), s1 = exp2f(mr[t][1] - mn1);
            float sum0 = 0.f, sum1 = 0.f;
#pragma unroll
            for (int j = 0; j < 8; j++) {
                sc[t][j][0] = exp2f(sc[t][j][0] - mn0); sum0 += sc[t][j][0];
                sc[t][j][1] = exp2f(sc[t][j][1] - mn0); sum0 += sc[t][j][1];
                sc[t][j][2] = exp2f(sc[t][j][2] - mn1); sum1 += sc[t][j][2];
                sc[t][j][3] = exp2f(sc[t][j][3] - mn1); sum1 += sc[t][j][3];
            }
            sum0 += __shfl_xor_sync(0xffffffffu, sum0, 1);
            sum0 += __shfl_xor_sync(0xffffffffu, sum0, 2);
            sum1 += __shfl_xor_sync(0xffffffffu, sum1, 1);
            sum1 += __shfl_xor_sync(0xffffffffu, sum1, 2);
            lr[t][0] = lr[t][0] * s0 + sum0; lr[t][1] = lr[t][1] * s1 + sum1;
            mr[t][0] = mn0; mr[t][1] = mn1;
#pragma unroll
            for (int j = 0; j < 8; j++) {
                O[t][j][0] *= s0; O[t][j][1] *= s0;
                O[t][j][2] *= s1; O[t][j][3] *= s1;
            }

            // P: C-frag -> A-frag repack
#pragma unroll
            for (int s = 0; s < 4; s++) {
                pf[t][s][0] = pack2(sc[t][2 * s][0],     sc[t][2 * s][1]);
                pf[t][s][1] = pack2(sc[t][2 * s][2],     sc[t][2 * s][3]);
                pf[t][s][2] = pack2(sc[t][2 * s + 1][0], sc[t][2 * s + 1][1]);
                pf[t][s][3] = pack2(sc[t][2 * s + 1][2], sc[t][2 * s + 1][3]);
            }
        }

        // ---- O += P @ V, one V-frag feeds 4 MMAs ----
        {
            uint32_t bf[2][4];
            ldsm4t(vsb[cur], bf[0]);
#pragma unroll
            for (int i = 0; i < 16; i++) {      // i = s*4 + g
                const int s = i >> 2, g = i & 3;
                if (i + 1 < 16) {
                    const int s2 = (i + 1) >> 2, g2 = (i + 1) & 3;
                    ldsm4t(vsb[cur] + (uint32_t)((16 * s2 * KLD + 16 * g2) * 2),
                           bf[(i + 1) & 1]);
                }
                mma16(O[0][2 * g],     pf[0][s], bf[i & 1]);
                mma16(O[0][2 * g + 1], pf[0][s], bf[i & 1] + 2);
                mma16(O[1][2 * g],     pf[1][s], bf[i & 1]);
                mma16(O[1][2 * g + 1], pf[1][s], bf[i & 1] + 2);
            }
        }
        __syncthreads();
    }

    // ---- Epilogue ----
#pragma unroll
    for (int t = 0; t < 2; t++) {
        const float i0 = 1.f / lr[t][0], i1 = 1.f / lr[t][1];
        __half* Op = AO + ((size_t)b * Ss + q0 + 32 * wp + 16 * t + (lane >> 2)) * Dd
                   + h * DHh + pcol;
#pragma unroll
        for (int j = 0; j < 8; j++) {
            *(__half2*)(Op + 8 * j) =
                __floats2half2_rn(O[t][j][0] * i0, O[t][j][1] * i0);
            *(__half2*)(Op + 8 * (size_t)Dd + 8 * j) =
                __floats2half2_rn(O[t][j][2] * i1, O[t][j][3] * i1);
        }
    }
}

// ---------------------------------------------------------------------------
extern "C" void kernel_launch(void* const* d_in, const int* in_sizes, int n_in,
                              void* d_out, int out_size)
{
    (void)in_sizes; (void)n_in; (void)out_size;
    const float* seq  = (const float*)d_in[0];
    const float* mask = (const float*)d_in[1];
    const float* Wq   = (const float*)d_in[2];
    const float* bq   = (const float*)d_in[3];
    const float* Wk   = (const float*)d_in[4];
    const float* bk   = (const float*)d_in[5];
    const float* Wv   = (const float*)d_in[6];
    const float* bv   = (const float*)d_in[7];
    const float* Wo   = (const float*)d_in[8];
    const float* bo   = (const float*)d_in[9];
    float* out = (float*)d_out;

    __half *Qg, *Kg, *Vg, *AOg;
    cudaGetSymbolAddress((void**)&Qg,  g_Q);
    cudaGetSymbolAddress((void**)&Kg,  g_K);
    cudaGetSymbolAddress((void**)&Vg,  g_V);
    cudaGetSymbolAddress((void**)&AOg, g_AO);

    // QKV projections in one launch (alpha_q = SCALE*log2e folded in)
    gemm_qkv<<<dim3(18, (Bb * Ss) / 128), 256>>>(
        seq, Wq, bq, Wk, bk, Wv, bv, Qg, Kg, Vg);

    // Flash attention: 4 warps x 32 Q rows, 2 CTAs/SM
    flash_f16<<<dim3(Ss / 128, Bb * Hh), 128>>>(Qg, Kg, Vg, mask, AOg);

    // Output projection
    gemm_out<<<dim3(Dd / 128, (Bb * Ss) / 128), 256>>>(AOg, Wo, bo, out);
}

// round 7
// speedup vs baseline: 6.6023x; 1.0701x over previous
#include <cuda_runtime.h>
#include <cuda_fp16.h>
#include <stdint.h>
#include <math.h>

// Problem constants
#define Bb  2
#define Ss  4096
#define Dd  768
#define Hh  12
#define DHh 64

#define LOG2E 1.44269504088896341f

// Scratch (device globals)
__device__ __half g_Q[(size_t)Bb * Hh * Ss * DHh];
__device__ __half g_K[(size_t)Bb * Hh * Ss * DHh];
__device__ __half g_V[(size_t)Bb * Hh * Ss * DHh];
__device__ __half g_AO[(size_t)Bb * Ss * Dd];
__device__ __half g_X[(size_t)Bb * Ss * Dd];          // seq in half
__device__ __half g_Wh[4][(size_t)Dd * Dd];           // Wq,Wk,Wv,Wo in half
__device__ __half g_maskh[(size_t)Ss * Ss];           // mask in half

// ---------------------------------------------------------------------------
__device__ __forceinline__ uint32_t sptr(const void* p) {
    return (uint32_t)__cvta_generic_to_shared(p);
}
__device__ __forceinline__ void ldsm4(uint32_t a, uint32_t* r) {
    asm volatile("ldmatrix.sync.aligned.m8n8.x4.shared.b16 {%0,%1,%2,%3}, [%4];"
                 : "=r"(r[0]), "=r"(r[1]), "=r"(r[2]), "=r"(r[3]) : "r"(a));
}
__device__ __forceinline__ void ldsm4t(uint32_t a, uint32_t* r) {
    asm volatile("ldmatrix.sync.aligned.m8n8.x4.trans.shared.b16 {%0,%1,%2,%3}, [%4];"
                 : "=r"(r[0]), "=r"(r[1]), "=r"(r[2]), "=r"(r[3]) : "r"(a));
}
__device__ __forceinline__ void mma16(float* d, const uint32_t* a, const uint32_t* b) {
    asm volatile("mma.sync.aligned.m16n8k16.row.col.f32.f16.f16.f32 "
                 "{%0,%1,%2,%3}, {%4,%5,%6,%7}, {%8,%9}, {%0,%1,%2,%3};"
                 : "+f"(d[0]), "+f"(d[1]), "+f"(d[2]), "+f"(d[3])
                 : "r"(a[0]), "r"(a[1]), "r"(a[2]), "r"(a[3]),
                   "r"(b[0]), "r"(b[1]));
}
__device__ __forceinline__ uint32_t pack2(float x, float y) {
    __half2 h = __floats2half2_rn(x, y);
    return *(uint32_t*)&h;
}
__device__ __forceinline__ void cp16(uint32_t s, const void* g) {
    asm volatile("cp.async.cg.shared.global [%0], [%1], 16;" :: "r"(s), "l"(g));
}
#define CP_COMMIT() asm volatile("cp.async.commit_group;")
#define CP_WAIT1()  asm volatile("cp.async.wait_group 1;")

// ---------------------------------------------------------------------------
// fp32 -> fp16 conversion (vectorized, grid-stride)
// ---------------------------------------------------------------------------
__global__ void cvt_f2h(const float4* __restrict__ in, __half2* __restrict__ out,
                        int n4)
{
    for (int i = blockIdx.x * blockDim.x + threadIdx.x; i < n4;
         i += gridDim.x * blockDim.x) {
        float4 v = in[i];
        out[2 * i]     = __floats2half2_rn(v.x, v.y);
        out[2 * i + 1] = __floats2half2_rn(v.z, v.w);
    }
}

// ---------------------------------------------------------------------------
// fp16 GEMM, pure cp.async staging: out = alpha * (X @ W^T + bias)
//   X: [M,768] half, W: [N,768] half, bias: [N] float.
//   BM=128, BN=128, BK=64, 2-stage cp.async double buffer.
//   mode 0: half out -> [B,H,S,DH]; mode 1: float out [M,768].
// ---------------------------------------------------------------------------
#define GKLD 72
#define GSZ (128 * GKLD)                 // halves per tensor tile
#define GEMM_DSMEM (2 * 2 * GSZ * 2)     // bytes: 73728
#define GNK (Dd / 64)                    // 12

__device__ __forceinline__ void gemm_body(
    const __half* __restrict__ X, const __half* __restrict__ W,
    const float* __restrict__ bias,
    float* __restrict__ outf, __half* __restrict__ outh,
    float alpha, int mode, int m0, int n0, __half* dsm)
{
    const int tid = threadIdx.x, lane = tid & 31, wp = tid >> 5;
    const int wm = (wp >> 2) * 64, wn = (wp & 3) * 32;

    // staging map: per tensor 1024 x 16B chunks; 4 per thread
    int row[4], col[4];
#pragma unroll
    for (int c = 0; c < 4; c++) {
        int idx = c * 256 + tid;
        row[c] = idx >> 3; col[c] = (idx & 7) * 8;   // halves
    }
    const __half* Xg = X + (size_t)m0 * Dd;
    const __half* Wg = W + (size_t)n0 * Dd;

    uint32_t adst[2][4], bdst[2][4];
#pragma unroll
    for (int st = 0; st < 2; st++)
#pragma unroll
        for (int c = 0; c < 4; c++) {
            adst[st][c] = sptr(dsm + st * 2 * GSZ + row[c] * GKLD + col[c]);
            bdst[st][c] = sptr(dsm + st * 2 * GSZ + GSZ + row[c] * GKLD + col[c]);
        }

    float acc[4][4][4];
#pragma unroll
    for (int i = 0; i < 4; i++)
#pragma unroll
        for (int j = 0; j < 4; j++)
#pragma unroll
            for (int r = 0; r < 4; r++) acc[i][j][r] = 0.f;

    // ldmatrix bases
    const int arow = wm + (lane & 15);
    const int acol = (lane & 16) ? 8 : 0;
    const int brow = wn + (lane & 7) + ((lane & 16) ? 8 : 0);
    const int bcol = (lane & 8) ? 8 : 0;
    uint32_t xsb[2], wsb[2];
#pragma unroll
    for (int st = 0; st < 2; st++) {
        xsb[st] = sptr(dsm + st * 2 * GSZ) + (uint32_t)((arow * GKLD + acol) * 2);
        wsb[st] = sptr(dsm + st * 2 * GSZ + GSZ) + (uint32_t)((brow * GKLD + bcol) * 2);
    }

    // preload stage 0
#pragma unroll
    for (int c = 0; c < 4; c++) {
        cp16(adst[0][c], Xg + (size_t)row[c] * Dd + col[c]);
        cp16(bdst[0][c], Wg + (size_t)row[c] * Dd + col[c]);
    }
    CP_COMMIT();

    for (int step = 0; step < GNK; step++) {
        const int cur = step & 1;
        if (step + 1 < GNK) {
            const int k0 = (step + 1) * 64;
#pragma unroll
            for (int c = 0; c < 4; c++) {
                cp16(adst[cur ^ 1][c], Xg + (size_t)row[c] * Dd + k0 + col[c]);
                cp16(bdst[cur ^ 1][c], Wg + (size_t)row[c] * Dd + k0 + col[c]);
            }
        }
        CP_COMMIT();
        CP_WAIT1();
        __syncthreads();

#pragma unroll
        for (int s = 0; s < 4; s++) {          // 4 x k16 within BK=64
            uint32_t af[4][4];
#pragma unroll
            for (int i = 0; i < 4; i++)
                ldsm4(xsb[cur] + (uint32_t)((16 * i * GKLD + 16 * s) * 2), af[i]);
#pragma unroll
            for (int g = 0; g < 2; g++) {
                uint32_t bf[4];
                ldsm4(wsb[cur] + (uint32_t)((16 * g * GKLD + 16 * s) * 2), bf);
#pragma unroll
                for (int i = 0; i < 4; i++) {
                    mma16(acc[i][2 * g],     af[i], bf);
                    mma16(acc[i][2 * g + 1], af[i], bf + 2);
                }
            }
        }
        __syncthreads();
    }

    // Epilogue
    const int mr = m0 + wm + (lane >> 2);
    const int nc = n0 + wn + 2 * (lane & 3);
#pragma unroll
    for (int j = 0; j < 4; j++) {
        const int n = nc + 8 * j;
        const float bv0 = bias[n], bv1 = bias[n + 1];
#pragma unroll
        for (int i = 0; i < 4; i++) {
            const int m = mr + 16 * i;
            const float r00 = alpha * (acc[i][j][0] + bv0);
            const float r01 = alpha * (acc[i][j][1] + bv1);
            const float r10 = alpha * (acc[i][j][2] + bv0);
            const float r11 = alpha * (acc[i][j][3] + bv1);
            if (mode == 0) {
                const int bb = m >> 12, ss = m & 4095, hh = n >> 6, dh = n & 63;
                __half* p = outh + ((size_t)(bb * Hh + hh) * Ss + ss) * DHh + dh;
                *(__half2*)p = __floats2half2_rn(r00, r01);
                *(__half2*)(p + 8 * DHh) = __floats2half2_rn(r10, r11);
            } else {
                float* p = outf + (size_t)m * Dd + n;
                *(float2*)p = make_float2(r00, r01);
                *(float2*)(p + 8 * Dd) = make_float2(r10, r11);
            }
        }
    }
}

// merged QKV: grid.x in [0,18) -> sel = x/6 picks Wq/Wk/Wv (pre-converted half)
__global__ void __launch_bounds__(256, 2) gemm_qkv(
    const __half* __restrict__ X,
    const float* __restrict__ bq, const float* __restrict__ bk,
    const float* __restrict__ bv,
    __half* __restrict__ Qo, __half* __restrict__ Ko, __half* __restrict__ Vo)
{
    extern __shared__ __half dsm[];
    const int sel = blockIdx.x / 6;
    const int n0 = (blockIdx.x % 6) * 128;
    const int m0 = blockIdx.y * 128;
    const __half* W = g_Wh[sel];
    const float* bias = (sel == 0) ? bq : (sel == 1) ? bk : bv;
    __half* out = (sel == 0) ? Qo : (sel == 1) ? Ko : Vo;
    const float alpha = (sel == 0) ? 0.125f * LOG2E : 1.0f;
    gemm_body(X, W, bias, nullptr, out, alpha, 0, m0, n0, dsm);
}

__global__ void __launch_bounds__(256, 2) gemm_out(
    const __half* __restrict__ X, const float* __restrict__ bias,
    float* __restrict__ out)
{
    extern __shared__ __half dsm[];
    gemm_body(X, g_Wh[3], bias, out, nullptr, 1.0f, 1,
              blockIdx.y * 128, blockIdx.x * 128, dsm);
}

// ---------------------------------------------------------------------------
// fp16 flash attention, FA2 warp layout: 4 warps x 32 Q rows, 2 CTAs/SM.
// cp.async double-buffered 64-row K/V tiles; exp2-domain softmax; half mask.
// ---------------------------------------------------------------------------
#define KLD 72
#define TILE_H (64 * KLD)

__global__ void __launch_bounds__(128, 2) flash_f16(
    const __half* __restrict__ Q, const __half* __restrict__ K,
    const __half* __restrict__ V, const __half* __restrict__ mask,
    __half* __restrict__ AO)
{
    __shared__ __half sm[2][2][TILE_H];

    const int tid = threadIdx.x, lane = tid & 31, wp = tid >> 5;
    const int q0 = blockIdx.x * 128;
    const int bh = blockIdx.y;
    const int b = bh / Hh, h = bh - b * Hh;

    const __half* Qp = Q + ((size_t)bh * Ss + q0) * DHh;
    const __half* Kp = K + (size_t)bh * Ss * DHh;
    const __half* Vp = V + (size_t)bh * Ss * DHh;

    // ---- Stage Q tile, load A-frags ----
    {
        __half* qstage = &sm[0][0][0];
#pragma unroll
        for (int c = 0; c < 8; c++) {
            int idx = c * 128 + tid;
            int r = idx >> 3, ch = (idx & 7) * 8;
            *(uint4*)&qstage[r * KLD + ch] = *(const uint4*)(Qp + (size_t)r * DHh + ch);
        }
    }
    __syncthreads();

    uint32_t qf[2][4][4];
#pragma unroll
    for (int t = 0; t < 2; t++) {
        const uint32_t qb = sptr(&sm[0][0][0]) +
            (uint32_t)(((32 * wp + 16 * t + (lane & 15)) * KLD +
                        ((lane & 16) ? 8 : 0)) * 2);
#pragma unroll
        for (int s = 0; s < 4; s++) ldsm4(qb + (uint32_t)(16 * s * 2), qf[t][s]);
    }
    __syncthreads();

    int srow[4], scol[4];
#pragma unroll
    for (int c = 0; c < 4; c++) {
        int idx = c * 128 + tid;
        srow[c] = idx >> 3; scol[c] = (idx & 7) * 8;
    }
    uint32_t kdst[2][4], vdst[2][4];
#pragma unroll
    for (int st = 0; st < 2; st++)
#pragma unroll
        for (int c = 0; c < 4; c++) {
            kdst[st][c] = sptr(&sm[st][0][srow[c] * KLD + scol[c]]);
            vdst[st][c] = sptr(&sm[st][1][srow[c] * KLD + scol[c]]);
        }

    const int krow = (lane & 7) + ((lane & 16) ? 8 : 0);
    const int kcol = (lane & 8) ? 8 : 0;
    const int vrow = lane & 15;
    const int vcol = (lane & 16) ? 8 : 0;
    uint32_t ksb[2], vsb[2];
#pragma unroll
    for (int st = 0; st < 2; st++) {
        ksb[st] = sptr(&sm[st][0][0]) + (uint32_t)((krow * KLD + kcol) * 2);
        vsb[st] = sptr(&sm[st][1][0]) + (uint32_t)((vrow * KLD + vcol) * 2);
    }

    float O[2][8][4];
#pragma unroll
    for (int t = 0; t < 2; t++)
#pragma unroll
        for (int j = 0; j < 8; j++)
#pragma unroll
            for (int r = 0; r < 4; r++) O[t][j][r] = 0.f;
    float mr[2][2] = {{-1e30f, -1e30f}, {-1e30f, -1e30f}};
    float lr[2][2] = {{0.f, 0.f}, {0.f, 0.f}};

    const int pcol = 2 * (lane & 3);
    const __half* mbase[2];
#pragma unroll
    for (int t = 0; t < 2; t++)
        mbase[t] = mask + (size_t)(q0 + 32 * wp + 16 * t + (lane >> 2)) * Ss + pcol;

    const int NT = Ss / 64;

#pragma unroll
    for (int c = 0; c < 4; c++) {
        cp16(kdst[0][c], Kp + (size_t)srow[c] * DHh + scol[c]);
        cp16(vdst[0][c], Vp + (size_t)srow[c] * DHh + scol[c]);
    }
    CP_COMMIT();

    for (int kt = 0; kt < NT; kt++) {
        const int cur = kt & 1;
        if (kt + 1 < NT) {
            const __half* Kn = Kp + (size_t)(kt + 1) * 64 * DHh;
            const __half* Vn = Vp + (size_t)(kt + 1) * 64 * DHh;
#pragma unroll
            for (int c = 0; c < 4; c++) {
                cp16(kdst[cur ^ 1][c], Kn + (size_t)srow[c] * DHh + scol[c]);
                cp16(vdst[cur ^ 1][c], Vn + (size_t)srow[c] * DHh + scol[c]);
            }
        }
        CP_COMMIT();
        CP_WAIT1();
        __syncthreads();

        // ---- Scores ----
        float sc[2][8][4];
#pragma unroll
        for (int t = 0; t < 2; t++)
#pragma unroll
            for (int j = 0; j < 8; j++)
#pragma unroll
                for (int r = 0; r < 4; r++) sc[t][j][r] = 0.f;

        {
            uint32_t bf[2][4];
            ldsm4(ksb[cur], bf[0]);
#pragma unroll
            for (int i = 0; i < 16; i++) {
                const int s = i >> 2, g = i & 3;
                if (i + 1 < 16) {
                    const int s2 = (i + 1) >> 2, g2 = (i + 1) & 3;
                    ldsm4(ksb[cur] + (uint32_t)((16 * g2 * KLD + 16 * s2) * 2),
                          bf[(i + 1) & 1]);
                }
                mma16(sc[0][2 * g],     qf[0][s], bf[i & 1]);
                mma16(sc[0][2 * g + 1], qf[0][s], bf[i & 1] + 2);
                mma16(sc[1][2 * g],     qf[1][s], bf[i & 1]);
                mma16(sc[1][2 * g + 1], qf[1][s], bf[i & 1] + 2);
            }
        }

        // ---- Mask (half, log2 domain) + online softmax ----
        uint32_t pf[2][4][4];
#pragma unroll
        for (int t = 0; t < 2; t++) {
            const __half* mp = mbase[t] + kt * 64;
#pragma unroll
            for (int j = 0; j < 8; j++) {
                float2 m0v = __half22float2(*(const __half2*)(mp + 8 * j));
                float2 m1v = __half22float2(*(const __half2*)(mp + 8 * (size_t)Ss + 8 * j));
                sc[t][j][0] = fmaf(m0v.x, LOG2E, sc[t][j][0]);
                sc[t][j][1] = fmaf(m0v.y, LOG2E, sc[t][j][1]);
                sc[t][j][2] = fmaf(m1v.x, LOG2E, sc[t][j][2]);
                sc[t][j][3] = fmaf(m1v.y, LOG2E, sc[t][j][3]);
            }

            float mx0 = -1e30f, mx1 = -1e30f;
#pragma unroll
            for (int j = 0; j < 8; j++) {
                mx0 = fmaxf(mx0, fmaxf(sc[t][j][0], sc[t][j][1]));
                mx1 = fmaxf(mx1, fmaxf(sc[t][j][2], sc[t][j][3]));
            }
            mx0 = fmaxf(mx0, __shfl_xor_sync(0xffffffffu, mx0, 1));
            mx0 = fmaxf(mx0, __shfl_xor_sync(0xffffffffu, mx0, 2));
            mx1 = fmaxf(mx1, __shfl_xor_sync(0xffffffffu, mx1, 1));
            mx1 = fmaxf(mx1, __shfl_xor_sync(0xffffffffu, mx1, 2));
            const float mn0 = fmaxf(mr[t][0], mx0), mn1 = fmaxf(mr[t][1], mx1);
            const float s0 = exp2f(mr[t][0] - mn0), s1 = exp2f(mr[t][1] - mn1);
            float sum0 = 0.f, sum1 = 0.f;
#pragma unroll
            for (int j = 0; j < 8; j++) {
                sc[t][j][0] = exp2f(sc[t][j][0] - mn0); sum0 += sc[t][j][0];
                sc[t][j][1] = exp2f(sc[t][j][1] - mn0); sum0 += sc[t][j][1];
                sc[t][j][2] = exp2f(sc[t][j][2] - mn1); sum1 += sc[t][j][2];
                sc[t][j][3] = exp2f(sc[t][j][3] - mn1); sum1 += sc[t][j][3];
            }
            sum0 += __shfl_xor_sync(0xffffffffu, sum0, 1);
            sum0 += __shfl_xor_sync(0xffffffffu, sum0, 2);
            sum1 += __shfl_xor_sync(0xffffffffu, sum1, 1);
            sum1 += __shfl_xor_sync(0xffffffffu, sum1, 2);
            lr[t][0] = lr[t][0] * s0 + sum0; lr[t][1] = lr[t][1] * s1 + sum1;
            mr[t][0] = mn0; mr[t][1] = mn1;
#pragma unroll
            for (int j = 0; j < 8; j++) {
                O[t][j][0] *= s0; O[t][j][1] *= s0;
                O[t][j][2] *= s1; O[t][j][3] *= s1;
            }

#pragma unroll
            for (int s = 0; s < 4; s++) {
                pf[t][s][0] = pack2(sc[t][2 * s][0],     sc[t][2 * s][1]);
                pf[t][s][1] = pack2(sc[t][2 * s][2],     sc[t][2 * s][3]);
                pf[t][s][2] = pack2(sc[t][2 * s + 1][0], sc[t][2 * s + 1][1]);
                pf[t][s][3] = pack2(sc[t][2 * s + 1][2], sc[t][2 * s + 1][3]);
            }
        }

        // ---- O += P @ V ----
        {
            uint32_t bf[2][4];
            ldsm4t(vsb[cur], bf[0]);
#pragma unroll
            for (int i = 0; i < 16; i++) {
                const int s = i >> 2, g = i & 3;
                if (i + 1 < 16) {
                    const int s2 = (i + 1) >> 2, g2 = (i + 1) & 3;
                    ldsm4t(vsb[cur] + (uint32_t)((16 * s2 * KLD + 16 * g2) * 2),
                           bf[(i + 1) & 1]);
                }
                mma16(O[0][2 * g],     pf[0][s], bf[i & 1]);
                mma16(O[0][2 * g + 1], pf[0][s], bf[i & 1] + 2);
                mma16(O[1][2 * g],     pf[1][s], bf[i & 1]);
                mma16(O[1][2 * g + 1], pf[1][s], bf[i & 1] + 2);
            }
        }
        __syncthreads();
    }

    // ---- Epilogue ----
#pragma unroll
    for (int t = 0; t < 2; t++) {
        const float i0 = 1.f / lr[t][0], i1 = 1.f / lr[t][1];
        __half* Op = AO + ((size_t)b * Ss + q0 + 32 * wp + 16 * t + (lane >> 2)) * Dd
                   + h * DHh + pcol;
#pragma unroll
        for (int j = 0; j < 8; j++) {
            *(__half2*)(Op + 8 * j) =
                __floats2half2_rn(O[t][j][0] * i0, O[t][j][1] * i0);
            *(__half2*)(Op + 8 * (size_t)Dd + 8 * j) =
                __floats2half2_rn(O[t][j][2] * i1, O[t][j][3] * i1);
        }
    }
}

// ---------------------------------------------------------------------------
extern "C" void kernel_launch(void* const* d_in, const int* in_sizes, int n_in,
                              void* d_out, int out_size)
{
    (void)in_sizes; (void)n_in; (void)out_size;
    const float* seq  = (const float*)d_in[0];
    const float* mask = (const float*)d_in[1];
    const float* Wq   = (const float*)d_in[2];
    const float* bq   = (const float*)d_in[3];
    const float* Wk   = (const float*)d_in[4];
    const float* bk   = (const float*)d_in[5];
    const float* Wv   = (const float*)d_in[6];
    const float* bv   = (const float*)d_in[7];
    const float* Wo   = (const float*)d_in[8];
    const float* bo   = (const float*)d_in[9];
    float* out = (float*)d_out;

    __half *Qg, *Kg, *Vg, *AOg, *Xg, *Mg, *Wg;
    cudaGetSymbolAddress((void**)&Qg,  g_Q);
    cudaGetSymbolAddress((void**)&Kg,  g_K);
    cudaGetSymbolAddress((void**)&Vg,  g_V);
    cudaGetSymbolAddress((void**)&AOg, g_AO);
    cudaGetSymbolAddress((void**)&Xg,  g_X);
    cudaGetSymbolAddress((void**)&Mg,  g_maskh);
    cudaGetSymbolAddress((void**)&Wg,  g_Wh);

    cudaFuncSetAttribute(gemm_qkv,
                         cudaFuncAttributeMaxDynamicSharedMemorySize, GEMM_DSMEM);
    cudaFuncSetAttribute(gemm_out,
                         cudaFuncAttributeMaxDynamicSharedMemorySize, GEMM_DSMEM);

    const size_t WSZ = (size_t)Dd * Dd;

    // fp32 -> fp16 conversions
    cvt_f2h<<<4096, 256>>>((const float4*)seq,  (__half2*)Xg,
                           (int)((size_t)Bb * Ss * Dd / 4));
    cvt_f2h<<<8192, 256>>>((const float4*)mask, (__half2*)Mg,
                           (int)((size_t)Ss * Ss / 4));
    cvt_f2h<<<576, 256>>>((const float4*)Wq, (__half2*)(Wg + 0 * WSZ), (int)(WSZ / 4));
    cvt_f2h<<<576, 256>>>((const float4*)Wk, (__half2*)(Wg + 1 * WSZ), (int)(WSZ / 4));
    cvt_f2h<<<576, 256>>>((const float4*)Wv, (__half2*)(Wg + 2 * WSZ), (int)(WSZ / 4));
    cvt_f2h<<<576, 256>>>((const float4*)Wo, (__half2*)(Wg + 3 * WSZ), (int)(WSZ / 4));

    // QKV projections (alpha_q = SCALE*log2e folded in)
    gemm_qkv<<<dim3(18, (Bb * Ss) / 128), 256, GEMM_DSMEM>>>(
        Xg, bq, bk, bv, Qg, Kg, Vg);

    // Flash attention
    flash_f16<<<dim3(Ss / 128, Bb * Hh), 128>>>(Qg, Kg, Vg, Mg, AOg);

    // Output projection
    gemm_out<<<dim3(Dd / 128, (Bb * Ss) / 128), 256, GEMM_DSMEM>>>(AOg, bo, out);
}

// round 8
// speedup vs baseline: 7.2812x; 1.1028x over previous
#include <cuda_runtime.h>
#include <cuda_fp16.h>
#include <stdint.h>
#include <math.h>

// Problem constants
#define Bb  2
#define Ss  4096
#define Dd  768
#define Hh  12
#define DHh 64

#define LOG2E 1.44269504088896341f

// Scratch (device globals)
__device__ __half g_Q[(size_t)Bb * Hh * Ss * DHh];
__device__ __half g_K[(size_t)Bb * Hh * Ss * DHh];
__device__ __half g_V[(size_t)Bb * Hh * Ss * DHh];
__device__ __half g_AO[(size_t)Bb * Ss * Dd];
__device__ __half g_X[(size_t)Bb * Ss * Dd];          // seq in half
__device__ __half g_Wh[4][(size_t)Dd * Dd];           // Wq,Wk,Wv,Wo in half
__device__ __half g_maskh[(size_t)Ss * Ss];           // mask in half

// ---------------------------------------------------------------------------
__device__ __forceinline__ uint32_t sptr(const void* p) {
    return (uint32_t)__cvta_generic_to_shared(p);
}
__device__ __forceinline__ void ldsm4(uint32_t a, uint32_t* r) {
    asm volatile("ldmatrix.sync.aligned.m8n8.x4.shared.b16 {%0,%1,%2,%3}, [%4];"
                 : "=r"(r[0]), "=r"(r[1]), "=r"(r[2]), "=r"(r[3]) : "r"(a));
}
__device__ __forceinline__ void ldsm4t(uint32_t a, uint32_t* r) {
    asm volatile("ldmatrix.sync.aligned.m8n8.x4.trans.shared.b16 {%0,%1,%2,%3}, [%4];"
                 : "=r"(r[0]), "=r"(r[1]), "=r"(r[2]), "=r"(r[3]) : "r"(a));
}
__device__ __forceinline__ void mma16(float* d, const uint32_t* a, const uint32_t* b) {
    asm volatile("mma.sync.aligned.m16n8k16.row.col.f32.f16.f16.f32 "
                 "{%0,%1,%2,%3}, {%4,%5,%6,%7}, {%8,%9}, {%0,%1,%2,%3};"
                 : "+f"(d[0]), "+f"(d[1]), "+f"(d[2]), "+f"(d[3])
                 : "r"(a[0]), "r"(a[1]), "r"(a[2]), "r"(a[3]),
                   "r"(b[0]), "r"(b[1]));
}
__device__ __forceinline__ uint32_t pack2(float x, float y) {
    __half2 h = __floats2half2_rn(x, y);
    return *(uint32_t*)&h;
}
__device__ __forceinline__ uint32_t h2exp2(uint32_t x) {
    uint32_t r;
    asm("ex2.approx.f16x2 %0, %1;" : "=r"(r) : "r"(x));
    return r;
}
__device__ __forceinline__ void cp16(uint32_t s, const void* g) {
    asm volatile("cp.async.cg.shared.global [%0], [%1], 16;" :: "r"(s), "l"(g));
}
#define CP_COMMIT() asm volatile("cp.async.commit_group;")
#define CP_WAIT1()  asm volatile("cp.async.wait_group 1;")

// ---------------------------------------------------------------------------
// fp32 -> fp16 conversions
// ---------------------------------------------------------------------------
__global__ void cvt_f2h(const float4* __restrict__ in, __half2* __restrict__ out,
                        int n4)
{
    for (int i = blockIdx.x * blockDim.x + threadIdx.x; i < n4;
         i += gridDim.x * blockDim.x) {
        float4 v = in[i];
        out[2 * i]     = __floats2half2_rn(v.x, v.y);
        out[2 * i + 1] = __floats2half2_rn(v.z, v.w);
    }
}
// all 4 weights in one launch: grid.y selects the weight
__global__ void cvt_w4(const float4* __restrict__ w0, const float4* __restrict__ w1,
                       const float4* __restrict__ w2, const float4* __restrict__ w3,
                       __half2* __restrict__ out, int n4)
{
    const float4* src = (blockIdx.y == 0) ? w0 : (blockIdx.y == 1) ? w1
                       : (blockIdx.y == 2) ? w2 : w3;
    __half2* dst = out + (size_t)blockIdx.y * n4 * 2;
    for (int i = blockIdx.x * blockDim.x + threadIdx.x; i < n4;
         i += gridDim.x * blockDim.x) {
        float4 v = src[i];
        dst[2 * i]     = __floats2half2_rn(v.x, v.y);
        dst[2 * i + 1] = __floats2half2_rn(v.z, v.w);
    }
}

// ---------------------------------------------------------------------------
// fp16 GEMM, pure cp.async staging (unchanged from R7, proven)
// ---------------------------------------------------------------------------
#define GKLD 72
#define GSZ (128 * GKLD)
#define GEMM_DSMEM (2 * 2 * GSZ * 2)
#define GNK (Dd / 64)

__device__ __forceinline__ void gemm_body(
    const __half* __restrict__ X, const __half* __restrict__ W,
    const float* __restrict__ bias,
    float* __restrict__ outf, __half* __restrict__ outh,
    float alpha, int mode, int m0, int n0, __half* dsm)
{
    const int tid = threadIdx.x, lane = tid & 31, wp = tid >> 5;
    const int wm = (wp >> 2) * 64, wn = (wp & 3) * 32;

    int row[4], col[4];
#pragma unroll
    for (int c = 0; c < 4; c++) {
        int idx = c * 256 + tid;
        row[c] = idx >> 3; col[c] = (idx & 7) * 8;
    }
    const __half* Xg = X + (size_t)m0 * Dd;
    const __half* Wg = W + (size_t)n0 * Dd;

    uint32_t adst[2][4], bdst[2][4];
#pragma unroll
    for (int st = 0; st < 2; st++)
#pragma unroll
        for (int c = 0; c < 4; c++) {
            adst[st][c] = sptr(dsm + st * 2 * GSZ + row[c] * GKLD + col[c]);
            bdst[st][c] = sptr(dsm + st * 2 * GSZ + GSZ + row[c] * GKLD + col[c]);
        }

    float acc[4][4][4];
#pragma unroll
    for (int i = 0; i < 4; i++)
#pragma unroll
        for (int j = 0; j < 4; j++)
#pragma unroll
            for (int r = 0; r < 4; r++) acc[i][j][r] = 0.f;

    const int arow = wm + (lane & 15);
    const int acol = (lane & 16) ? 8 : 0;
    const int brow = wn + (lane & 7) + ((lane & 16) ? 8 : 0);
    const int bcol = (lane & 8) ? 8 : 0;
    uint32_t xsb[2], wsb[2];
#pragma unroll
    for (int st = 0; st < 2; st++) {
        xsb[st] = sptr(dsm + st * 2 * GSZ) + (uint32_t)((arow * GKLD + acol) * 2);
        wsb[st] = sptr(dsm + st * 2 * GSZ + GSZ) + (uint32_t)((brow * GKLD + bcol) * 2);
    }

#pragma unroll
    for (int c = 0; c < 4; c++) {
        cp16(adst[0][c], Xg + (size_t)row[c] * Dd + col[c]);
        cp16(bdst[0][c], Wg + (size_t)row[c] * Dd + col[c]);
    }
    CP_COMMIT();

    for (int step = 0; step < GNK; step++) {
        const int cur = step & 1;
        if (step + 1 < GNK) {
            const int k0 = (step + 1) * 64;
#pragma unroll
            for (int c = 0; c < 4; c++) {
                cp16(adst[cur ^ 1][c], Xg + (size_t)row[c] * Dd + k0 + col[c]);
                cp16(bdst[cur ^ 1][c], Wg + (size_t)row[c] * Dd + k0 + col[c]);
            }
        }
        CP_COMMIT();
        CP_WAIT1();
        __syncthreads();

#pragma unroll
        for (int s = 0; s < 4; s++) {
            uint32_t af[4][4];
#pragma unroll
            for (int i = 0; i < 4; i++)
                ldsm4(xsb[cur] + (uint32_t)((16 * i * GKLD + 16 * s) * 2), af[i]);
#pragma unroll
            for (int g = 0; g < 2; g++) {
                uint32_t bf[4];
                ldsm4(wsb[cur] + (uint32_t)((16 * g * GKLD + 16 * s) * 2), bf);
#pragma unroll
                for (int i = 0; i < 4; i++) {
                    mma16(acc[i][2 * g],     af[i], bf);
                    mma16(acc[i][2 * g + 1], af[i], bf + 2);
                }
            }
        }
        __syncthreads();
    }

    const int mr = m0 + wm + (lane >> 2);
    const int nc = n0 + wn + 2 * (lane & 3);
#pragma unroll
    for (int j = 0; j < 4; j++) {
        const int n = nc + 8 * j;
        const float bv0 = bias[n], bv1 = bias[n + 1];
#pragma unroll
        for (int i = 0; i < 4; i++) {
            const int m = mr + 16 * i;
            const float r00 = alpha * (acc[i][j][0] + bv0);
            const float r01 = alpha * (acc[i][j][1] + bv1);
            const float r10 = alpha * (acc[i][j][2] + bv0);
            const float r11 = alpha * (acc[i][j][3] + bv1);
            if (mode == 0) {
                const int bb = m >> 12, ss = m & 4095, hh = n >> 6, dh = n & 63;
                __half* p = outh + ((size_t)(bb * Hh + hh) * Ss + ss) * DHh + dh;
                *(__half2*)p = __floats2half2_rn(r00, r01);
                *(__half2*)(p + 8 * DHh) = __floats2half2_rn(r10, r11);
            } else {
                float* p = outf + (size_t)m * Dd + n;
                *(float2*)p = make_float2(r00, r01);
                *(float2*)(p + 8 * Dd) = make_float2(r10, r11);
            }
        }
    }
}

__global__ void __launch_bounds__(256, 2) gemm_qkv(
    const __half* __restrict__ X,
    const float* __restrict__ bq, const float* __restrict__ bk,
    const float* __restrict__ bv,
    __half* __restrict__ Qo, __half* __restrict__ Ko, __half* __restrict__ Vo)
{
    extern __shared__ __half dsm[];
    const int sel = blockIdx.x / 6;
    const int n0 = (blockIdx.x % 6) * 128;
    const int m0 = blockIdx.y * 128;
    const __half* W = g_Wh[sel];
    const float* bias = (sel == 0) ? bq : (sel == 1) ? bk : bv;
    __half* out = (sel == 0) ? Qo : (sel == 1) ? Ko : Vo;
    const float alpha = (sel == 0) ? 0.125f * LOG2E : 1.0f;
    gemm_body(X, W, bias, nullptr, out, alpha, 0, m0, n0, dsm);
}

__global__ void __launch_bounds__(256, 2) gemm_out(
    const __half* __restrict__ X, const float* __restrict__ bias,
    float* __restrict__ out)
{
    extern __shared__ __half dsm[];
    gemm_body(X, g_Wh[3], bias, out, nullptr, 1.0f, 1,
              blockIdx.y * 128, blockIdx.x * 128, dsm);
}

// ---------------------------------------------------------------------------
// fp16 flash attention: FA2 layout (4 warps x 32 Q rows), 2 CTAs/SM,
// cp.async double-buffered K/V; half2 approx exp; row sums via ones-column MMA.
// V tile padded to KLD=88; dh col 64 holds 1.0 -> PV MMA group g=4 accumulates
// row sums into Osum (same rescale recurrence as O).
// ---------------------------------------------------------------------------
#define KLD 88
#define TILE_H (64 * KLD)

__global__ void __launch_bounds__(128, 2) flash_f16(
    const __half* __restrict__ Q, const __half* __restrict__ K,
    const __half* __restrict__ V, const __half* __restrict__ mask,
    __half* __restrict__ AO)
{
    __shared__ __half sm[2][2][TILE_H];

    const int tid = threadIdx.x, lane = tid & 31, wp = tid >> 5;
    const int q0 = blockIdx.x * 128;
    const int bh = blockIdx.y;
    const int b = bh / Hh, h = bh - b * Hh;

    const __half* Qp = Q + ((size_t)bh * Ss + q0) * DHh;
    const __half* Kp = K + (size_t)bh * Ss * DHh;
    const __half* Vp = V + (size_t)bh * Ss * DHh;

    // ---- Stage Q tile, load A-frags ----
    {
        __half* qstage = &sm[0][0][0];
#pragma unroll
        for (int c = 0; c < 8; c++) {
            int idx = c * 128 + tid;
            int r = idx >> 3, ch = (idx & 7) * 8;
            *(uint4*)&qstage[r * KLD + ch] = *(const uint4*)(Qp + (size_t)r * DHh + ch);
        }
    }
    __syncthreads();

    uint32_t qf[2][4][4];
#pragma unroll
    for (int t = 0; t < 2; t++) {
        const uint32_t qb = sptr(&sm[0][0][0]) +
            (uint32_t)(((32 * wp + 16 * t + (lane & 15)) * KLD +
                        ((lane & 16) ? 8 : 0)) * 2);
#pragma unroll
        for (int s = 0; s < 4; s++) ldsm4(qb + (uint32_t)(16 * s * 2), qf[t][s]);
    }
    __syncthreads();

    // ---- Init ones-column region of V buffers (cols 64..79, both stages) ----
    {
        const int st = tid >> 6, r = tid & 63;   // 128 threads = 2 stages x 64 rows
        __half2* p = (__half2*)&sm[st][1][r * KLD + 64];
        p[0] = __floats2half2_rn(1.f, 0.f);
#pragma unroll
        for (int j = 1; j < 8; j++) p[j] = __floats2half2_rn(0.f, 0.f);
    }

    int srow[4], scol[4];
#pragma unroll
    for (int c = 0; c < 4; c++) {
        int idx = c * 128 + tid;
        srow[c] = idx >> 3; scol[c] = (idx & 7) * 8;
    }
    uint32_t kdst[2][4], vdst[2][4];
#pragma unroll
    for (int st = 0; st < 2; st++)
#pragma unroll
        for (int c = 0; c < 4; c++) {
            kdst[st][c] = sptr(&sm[st][0][srow[c] * KLD + scol[c]]);
            vdst[st][c] = sptr(&sm[st][1][srow[c] * KLD + scol[c]]);
        }

    const int krow = (lane & 7) + ((lane & 16) ? 8 : 0);
    const int kcol = (lane & 8) ? 8 : 0;
    const int vrow = lane & 15;
    const int vcol = (lane & 16) ? 8 : 0;
    uint32_t ksb[2], vsb[2];
#pragma unroll
    for (int st = 0; st < 2; st++) {
        ksb[st] = sptr(&sm[st][0][0]) + (uint32_t)((krow * KLD + kcol) * 2);
        vsb[st] = sptr(&sm[st][1][0]) + (uint32_t)((vrow * KLD + vcol) * 2);
    }

    float O[2][8][4];
    float Osum[2][4];
#pragma unroll
    for (int t = 0; t < 2; t++) {
#pragma unroll
        for (int j = 0; j < 8; j++)
#pragma unroll
            for (int r = 0; r < 4; r++) O[t][j][r] = 0.f;
#pragma unroll
        for (int r = 0; r < 4; r++) Osum[t][r] = 0.f;
    }
    float mr[2][2] = {{-1e30f, -1e30f}, {-1e30f, -1e30f}};

    const int pcol = 2 * (lane & 3);
    const __half* mbase[2];
#pragma unroll
    for (int t = 0; t < 2; t++)
        mbase[t] = mask + (size_t)(q0 + 32 * wp + 16 * t + (lane >> 2)) * Ss + pcol;

    const int NT = Ss / 64;

#pragma unroll
    for (int c = 0; c < 4; c++) {
        cp16(kdst[0][c], Kp + (size_t)srow[c] * DHh + scol[c]);
        cp16(vdst[0][c], Vp + (size_t)srow[c] * DHh + scol[c]);
    }
    CP_COMMIT();

    for (int kt = 0; kt < NT; kt++) {
        const int cur = kt & 1;
        if (kt + 1 < NT) {
            const __half* Kn = Kp + (size_t)(kt + 1) * 64 * DHh;
            const __half* Vn = Vp + (size_t)(kt + 1) * 64 * DHh;
#pragma unroll
            for (int c = 0; c < 4; c++) {
                cp16(kdst[cur ^ 1][c], Kn + (size_t)srow[c] * DHh + scol[c]);
                cp16(vdst[cur ^ 1][c], Vn + (size_t)srow[c] * DHh + scol[c]);
            }
        }
        CP_COMMIT();
        CP_WAIT1();
        __syncthreads();

        // ---- Scores ----
        float sc[2][8][4];
#pragma unroll
        for (int t = 0; t < 2; t++)
#pragma unroll
            for (int j = 0; j < 8; j++)
#pragma unroll
                for (int r = 0; r < 4; r++) sc[t][j][r] = 0.f;

        {
            uint32_t bf[2][4];
            ldsm4(ksb[cur], bf[0]);
#pragma unroll
            for (int i = 0; i < 16; i++) {
                const int s = i >> 2, g = i & 3;
                if (i + 1 < 16) {
                    const int s2 = (i + 1) >> 2, g2 = (i + 1) & 3;
                    ldsm4(ksb[cur] + (uint32_t)((16 * g2 * KLD + 16 * s2) * 2),
                          bf[(i + 1) & 1]);
                }
                mma16(sc[0][2 * g],     qf[0][s], bf[i & 1]);
                mma16(sc[0][2 * g + 1], qf[0][s], bf[i & 1] + 2);
                mma16(sc[1][2 * g],     qf[1][s], bf[i & 1]);
                mma16(sc[1][2 * g + 1], qf[1][s], bf[i & 1] + 2);
            }
        }

        // ---- Mask + online softmax (half2 approx exp; sums via PV MMA) ----
        uint32_t pf[2][4][4];
#pragma unroll
        for (int t = 0; t < 2; t++) {
            const __half* mp = mbase[t] + kt * 64;
#pragma unroll
            for (int j = 0; j < 8; j++) {
                float2 m0v = __half22float2(*(const __half2*)(mp + 8 * j));
                float2 m1v = __half22float2(*(const __half2*)(mp + 8 * (size_t)Ss + 8 * j));
                sc[t][j][0] = fmaf(m0v.x, LOG2E, sc[t][j][0]);
                sc[t][j][1] = fmaf(m0v.y, LOG2E, sc[t][j][1]);
                sc[t][j][2] = fmaf(m1v.x, LOG2E, sc[t][j][2]);
                sc[t][j][3] = fmaf(m1v.y, LOG2E, sc[t][j][3]);
            }

            float mx0 = -1e30f, mx1 = -1e30f;
#pragma unroll
            for (int j = 0; j < 8; j++) {
                mx0 = fmaxf(mx0, fmaxf(sc[t][j][0], sc[t][j][1]));
                mx1 = fmaxf(mx1, fmaxf(sc[t][j][2], sc[t][j][3]));
            }
            mx0 = fmaxf(mx0, __shfl_xor_sync(0xffffffffu, mx0, 1));
            mx0 = fmaxf(mx0, __shfl_xor_sync(0xffffffffu, mx0, 2));
            mx1 = fmaxf(mx1, __shfl_xor_sync(0xffffffffu, mx1, 1));
            mx1 = fmaxf(mx1, __shfl_xor_sync(0xffffffffu, mx1, 2));
            const float mn0 = fmaxf(mr[t][0], mx0), mn1 = fmaxf(mr[t][1], mx1);
            const float s0 = exp2f(mr[t][0] - mn0), s1 = exp2f(mr[t][1] - mn1);
            mr[t][0] = mn0; mr[t][1] = mn1;

            // P = exp2(sc - mn) in half2, already A-frag packed
#pragma unroll
            for (int s = 0; s < 4; s++) {
                pf[t][s][0] = h2exp2(pack2(sc[t][2 * s][0] - mn0,
                                           sc[t][2 * s][1] - mn0));
                pf[t][s][1] = h2exp2(pack2(sc[t][2 * s][2] - mn1,
                                           sc[t][2 * s][3] - mn1));
                pf[t][s][2] = h2exp2(pack2(sc[t][2 * s + 1][0] - mn0,
                                           sc[t][2 * s + 1][1] - mn0));
                pf[t][s][3] = h2exp2(pack2(sc[t][2 * s + 1][2] - mn1,
                                           sc[t][2 * s + 1][3] - mn1));
            }

            // rescale O and Osum
#pragma unroll
            for (int j = 0; j < 8; j++) {
                O[t][j][0] *= s0; O[t][j][1] *= s0;
                O[t][j][2] *= s1; O[t][j][3] *= s1;
            }
            Osum[t][0] *= s0; Osum[t][1] *= s0;
            Osum[t][2] *= s1; Osum[t][3] *= s1;
        }

        // ---- O += P @ [V | 1], 5 n-groups (g=4 is the ones column) ----
        {
            uint32_t bf[2][4];
            ldsm4t(vsb[cur], bf[0]);
#pragma unroll
            for (int i = 0; i < 20; i++) {      // i = s*5 + g
                const int s = i / 5, g = i % 5;
                if (i + 1 < 20) {
                    const int s2 = (i + 1) / 5, g2 = (i + 1) % 5;
                    ldsm4t(vsb[cur] + (uint32_t)((16 * s2 * KLD + 16 * g2) * 2),
                           bf[(i + 1) & 1]);
                }
                if (g < 4) {
                    mma16(O[0][2 * g],     pf[0][s], bf[i & 1]);
                    mma16(O[0][2 * g + 1], pf[0][s], bf[i & 1] + 2);
                    mma16(O[1][2 * g],     pf[1][s], bf[i & 1]);
                    mma16(O[1][2 * g + 1], pf[1][s], bf[i & 1] + 2);
                } else {
                    mma16(Osum[0], pf[0][s], bf[i & 1]);
                    mma16(Osum[1], pf[1][s], bf[i & 1]);
                }
            }
        }
        __syncthreads();
    }

    // ---- Epilogue: l lives in Osum col 64 (lanes with lane&3==0) ----
#pragma unroll
    for (int t = 0; t < 2; t++) {
        const float l0 = __shfl_sync(0xffffffffu, Osum[t][0], lane & 28);
        const float l1 = __shfl_sync(0xffffffffu, Osum[t][2], lane & 28);
        const float i0 = 1.f / l0, i1 = 1.f / l1;
        __half* Op = AO + ((size_t)b * Ss + q0 + 32 * wp + 16 * t + (lane >> 2)) * Dd
                   + h * DHh + pcol;
#pragma unroll
        for (int j = 0; j < 8; j++) {
            *(__half2*)(Op + 8 * j) =
                __floats2half2_rn(O[t][j][0] * i0, O[t][j][1] * i0);
            *(__half2*)(Op + 8 * (size_t)Dd + 8 * j) =
                __floats2half2_rn(O[t][j][2] * i1, O[t][j][3] * i1);
        }
    }
}

// ---------------------------------------------------------------------------
extern "C" void kernel_launch(void* const* d_in, const int* in_sizes, int n_in,
                              void* d_out, int out_size)
{
    (void)in_sizes; (void)n_in; (void)out_size;
    const float* seq  = (const float*)d_in[0];
    const float* mask = (const float*)d_in[1];
    const float* Wq   = (const float*)d_in[2];
    const float* bq   = (const float*)d_in[3];
    const float* Wk   = (const float*)d_in[4];
    const float* bk   = (const float*)d_in[5];
    const float* Wv   = (const float*)d_in[6];
    const float* bv   = (const float*)d_in[7];
    const float* Wo   = (const float*)d_in[8];
    const float* bo   = (const float*)d_in[9];
    float* out = (float*)d_out;

    __half *Qg, *Kg, *Vg, *AOg, *Xg, *Mg, *Wg;
    cudaGetSymbolAddress((void**)&Qg,  g_Q);
    cudaGetSymbolAddress((void**)&Kg,  g_K);
    cudaGetSymbolAddress((void**)&Vg,  g_V);
    cudaGetSymbolAddress((void**)&AOg, g_AO);
    cudaGetSymbolAddress((void**)&Xg,  g_X);
    cudaGetSymbolAddress((void**)&Mg,  g_maskh);
    cudaGetSymbolAddress((void**)&Wg,  g_Wh);

    cudaFuncSetAttribute(gemm_qkv,
                         cudaFuncAttributeMaxDynamicSharedMemorySize, GEMM_DSMEM);
    cudaFuncSetAttribute(gemm_out,
                         cudaFuncAttributeMaxDynamicSharedMemorySize, GEMM_DSMEM);

    const size_t WSZ = (size_t)Dd * Dd;

    // fp32 -> fp16 conversions
    cvt_f2h<<<4096, 256>>>((const float4*)seq,  (__half2*)Xg,
                           (int)((size_t)Bb * Ss * Dd / 4));
    cvt_f2h<<<8192, 256>>>((const float4*)mask, (__half2*)Mg,
                           (int)((size_t)Ss * Ss / 4));
    cvt_w4<<<dim3(144, 4), 256>>>((const float4*)Wq, (const float4*)Wk,
                                  (const float4*)Wv, (const float4*)Wo,
                                  (__half2*)Wg, (int)(WSZ / 4));

    // QKV projections (alpha_q = SCALE*log2e folded in)
    gemm_qkv<<<dim3(18, (Bb * Ss) / 128), 256, GEMM_DSMEM>>>(
        Xg, bq, bk, bv, Qg, Kg, Vg);

    // Flash attention
    flash_f16<<<dim3(Ss / 128, Bb * Hh), 128>>>(Qg, Kg, Vg, Mg, AOg);

    // Output projection
    gemm_out<<<dim3(Dd / 128, (Bb * Ss) / 128), 256, GEMM_DSMEM>>>(AOg, bo, out);
}